// round 13
// baseline (speedup 1.0000x reference)
#include <cuda_runtime.h>
#include <cuda_fp16.h>
#include <math.h>

// Problem constants (fixed-shape problem)
#define BB 4
#define HH_ 180
#define WW 180
#define SPATIAL (HH_ * WW)       // 32400
#define C_L 128
#define C_C 128
#define CH_ALL 512
#define CH_HID 170
#define C_OUT 256

typedef unsigned int u32;
typedef unsigned long long u64;

// ---- fused kernel smem map (bytes) ----
#define SM_AH 0
#define SM_B  32768
#define SM_SB 98304
#define SMEM_TOTAL 98560

#define GRID_F 304    // 2 CTAs x 152 SMs (GB300)
#define MM_CHUNK 128

// ---------------- device scratch ----------------------------------------------
__device__ __align__(16) float g_imgT[SPATIAL * C_C];     // img batch0 [pixel][chan]
// split min/max key arrays: [b][c], c: 0..127 lidar, 128..255 cam (encoded)
__device__ unsigned g_kmin[BB * 256];
__device__ unsigned g_kmax[BB * 256];
__device__ __align__(16) float g_att_l[BB * C_L];
__device__ __align__(16) float g_att_c[BB * C_C];
__device__ __align__(16) float g_hc[BB * C_OUT];          // per-batch GEMM1 cam bias
__device__ __align__(16) __half g_B1[65536];              // pre-swizzled fp16 weights
__device__ __align__(16) __half g_B2[65536];

// ---------------- helpers -------------------------------------------------------
__device__ __forceinline__ u32 smem_u32(const void* p) {
    u32 r;
    asm("{ .reg .u64 t; cvta.to.shared.u64 t, %1; cvt.u32.u64 %0, t; }" : "=r"(r) : "l"(p));
    return r;
}
__device__ __forceinline__ void cp16(u32 dst, const void* src) {
    asm volatile("cp.async.cg.shared.global [%0], [%1], 16;" :: "r"(dst), "l"(src) : "memory");
}
__device__ __forceinline__ void cp_commit() { asm volatile("cp.async.commit_group;" ::: "memory"); }
__device__ __forceinline__ void cp_wait0()  { asm volatile("cp.async.wait_group 0;" ::: "memory"); }
__device__ __forceinline__ void cp_wait1()  { asm volatile("cp.async.wait_group 1;" ::: "memory"); }

__device__ __forceinline__ void ldsm4(u32 a, u32 &r0, u32 &r1, u32 &r2, u32 &r3) {
    asm volatile("ldmatrix.sync.aligned.m8n8.x4.shared.b16 {%0,%1,%2,%3}, [%4];"
                 : "=r"(r0), "=r"(r1), "=r"(r2), "=r"(r3) : "r"(a));
}
__device__ __forceinline__ void mma16816(float* c, const u32* a, u32 b0, u32 b1) {
    asm volatile("mma.sync.aligned.m16n8k16.row.col.f32.f16.f16.f32 "
                 "{%0,%1,%2,%3}, {%4,%5,%6,%7}, {%8,%9}, {%0,%1,%2,%3};"
                 : "+f"(c[0]), "+f"(c[1]), "+f"(c[2]), "+f"(c[3])
                 : "r"(a[0]), "r"(a[1]), "r"(a[2]), "r"(a[3]), "r"(b0), "r"(b1));
}

// Order-preserving float <-> uint encoding for atomic min/max
__device__ __forceinline__ unsigned enc_f(float x) {
    unsigned u = __float_as_uint(x);
    return (u & 0x80000000u) ? ~u : (u | 0x80000000u);
}
__device__ __forceinline__ float dec_f(unsigned k) {
    unsigned u = (k & 0x80000000u) ? (k ^ 0x80000000u) : ~k;
    return __uint_as_float(u);
}
__device__ __forceinline__ void min4(float4 &d, float4 v) {
    d.x = fminf(d.x, v.x); d.y = fminf(d.y, v.y);
    d.z = fminf(d.z, v.z); d.w = fminf(d.w, v.w);
}
__device__ __forceinline__ void max4(float4 &d, float4 v) {
    d.x = fmaxf(d.x, v.x); d.y = fmaxf(d.y, v.y);
    d.z = fmaxf(d.z, v.z); d.w = fmaxf(d.w, v.w);
}

// ---------------- kernel 0: init key arrays -------------------------------------
__global__ void initk_kernel() {
    for (int i = threadIdx.x; i < BB * 256; i += 256) {
        g_kmin[i] = 0xFFFFFFFFu;
        g_kmax[i] = 0x00000000u;
    }
}

// ---------------- kernel A: prep = lidar-minmax + transpose + weight_prep -------
// blocks [0, nchunks)            : lidar min/max scan (independent of transpose)
// blocks [nchunks, +4052)        : transpose img_bev[0] [C][P] -> [P][C]
// blocks [+512)                  : weight prep (fp16 + pre-swizzle)
#define TP_BLKS (((SPATIAL + 31) / 32) * 4)    // 1013 * 4 = 4052
__global__ void __launch_bounds__(256) prep_kernel(
    const float* __restrict__ img,
    const float* __restrict__ Wf1, const float* __restrict__ Wf2,
    const float* __restrict__ lidar, const int* __restrict__ batch_idx,
    int N, int nchunks)
{
    int blk = blockIdx.x;
    int tid = threadIdx.x;
    if (blk < nchunks) {
        // ---- lidar min/max for one 128-row chunk ----
        __shared__ int sb[MM_CHUNK];
        __shared__ float red[2][8][128];
        int n0 = blk * MM_CHUNK;
        int cnt = N - n0; if (cnt > MM_CHUNK) cnt = MM_CHUNK;
        if (cnt <= 0) return;
        if (tid < cnt) sb[tid] = batch_idx[n0 + tid];
        __syncthreads();
        if (cnt == MM_CHUNK && sb[0] == sb[MM_CHUNK - 1]) {
            int rg = tid >> 5, c4 = tid & 31;
            const float4* lid4 = (const float4*)lidar;
            float4 mn = make_float4( INFINITY,  INFINITY,  INFINITY,  INFINITY);
            float4 mx = make_float4(-INFINITY, -INFINITY, -INFINITY, -INFINITY);
#pragma unroll 4
            for (int i = 0; i < MM_CHUNK / 8; ++i) {
                int row = i * 8 + rg;
                float4 v = lid4[(size_t)(n0 + row) * 32 + c4];
                min4(mn, v); max4(mx, v);
            }
            int ch = c4 * 4;
            *(float4*)&red[0][rg][ch] = mn;
            *(float4*)&red[1][rg][ch] = mx;
            __syncthreads();
            if (tid < 128) {
                float m0 = red[0][0][tid], m1 = red[1][0][tid];
#pragma unroll
                for (int g = 1; g < 8; ++g) {
                    m0 = fminf(m0, red[0][g][tid]);
                    m1 = fmaxf(m1, red[1][g][tid]);
                }
                atomicMin(&g_kmin[sb[0] * 256 + tid], enc_f(m0));
                atomicMax(&g_kmax[sb[0] * 256 + tid], enc_f(m1));
            }
        } else if (tid < 128) {
            float mn = INFINITY, mx = -INFINITY;
            int cur = sb[0];
            for (int i = 0; i < cnt; ++i) {
                int b = sb[i];
                if (b != cur) {
                    atomicMin(&g_kmin[cur * 256 + tid], enc_f(mn));
                    atomicMax(&g_kmax[cur * 256 + tid], enc_f(mx));
                    cur = b; mn = INFINITY; mx = -INFINITY;
                }
                float v = lidar[(size_t)(n0 + i) * C_L + tid];
                mn = fminf(mn, v); mx = fmaxf(mx, v);
            }
            atomicMin(&g_kmin[cur * 256 + tid], enc_f(mn));
            atomicMax(&g_kmax[cur * 256 + tid], enc_f(mx));
        }
    } else if (blk < nchunks + TP_BLKS) {
        // ---- transpose ----
        __shared__ float tile[32][33];
        int b2 = blk - nchunks;
        int bx = b2 % 1013, by = b2 / 1013;
        int p0 = bx * 32, c0 = by * 32;
        int tx = tid & 31, ty = tid >> 5;
#pragma unroll
        for (int j = 0; j < 4; ++j) {
            int c = c0 + ty + j * 8;
            int p = p0 + tx;
            if (p < SPATIAL) tile[ty + j * 8][tx] = img[c * SPATIAL + p];
        }
        __syncthreads();
#pragma unroll
        for (int j = 0; j < 4; ++j) {
            int p = p0 + ty + j * 8;
            int c = c0 + tx;
            if (p < SPATIAL) g_imgT[p * C_C + c] = tile[tx][ty + j * 8];
        }
    } else {
        // ---- weight prep ----
        int idx = (blk - nchunks - TP_BLKS) * 256 + tid;   // 2 * 65536
        int mat = idx >> 16;
        int rem = idx & 65535;
        int k = rem >> 8;
        int n = rem & 255;
        const float* W = mat ? Wf2 : Wf1;
        __half hv = __float2half_rn(W[k * 256 + n]);
        int p = k >> 6, k8l = (k >> 3) & 7, e = k & 7;
        u32 off = (u32)p * 32768u + (u32)n * 128u + ((u32)(k8l ^ (n & 7)) << 4) + (u32)e * 2u;
        __half* wim = mat ? g_B2 : g_B1;
        *(unsigned short*)((char*)wim + off) = *(unsigned short*)&hv;
    }
}

// ---------------- kernel B: cam min/max (b=0 chunks only + const_cam) -----------
// For b>=1: every voxel gathers pixel 32398 (clamp) -> cam min=max=imgT[32398],
// handled by the extra block; chunks starting at b>=1 exit immediately.
__global__ void __launch_bounds__(256) camminmax_kernel(
    const int* __restrict__ batch_idx,
    const int* __restrict__ y_idx, const int* __restrict__ x_idx,
    int N, int nchunks)
{
    int tid = threadIdx.x;
    if ((int)blockIdx.x == nchunks) {    // const_cam block
        for (int i = tid; i < 384; i += 256) {
            int b = 1 + (i >> 7);
            int c = i & 127;
            unsigned e = enc_f(g_imgT[(size_t)(SPATIAL - 2) * C_C + c]);
            atomicMin(&g_kmin[b * 256 + 128 + c], e);
            atomicMax(&g_kmax[b * 256 + 128 + c], e);
        }
        return;
    }
    int n0 = blockIdx.x * MM_CHUNK;
    int cnt = N - n0; if (cnt > MM_CHUNK) cnt = MM_CHUNK;
    if (cnt <= 0) return;
    if (batch_idx[n0] >= 1) return;      // whole chunk b>=1 (sorted) -> constant cam

    __shared__ int sb[MM_CHUNK];
    __shared__ int sr[MM_CHUNK];
    __shared__ float red[2][8][128];
    if (tid < cnt) {
        int n = n0 + tid;
        int b = batch_idx[n];
        int r = b * SPATIAL + y_idx[n] * WW + x_idx[n];
        if (r > SPATIAL - 2) r = SPATIAL - 2;
        sb[tid] = b; sr[tid] = r;
    }
    __syncthreads();

    if (cnt == MM_CHUNK && sb[MM_CHUNK - 1] == 0) {
        int rg = tid >> 5, c4 = tid & 31;
        const float4* img4 = (const float4*)g_imgT;
        float4 mn = make_float4( INFINITY,  INFINITY,  INFINITY,  INFINITY);
        float4 mx = make_float4(-INFINITY, -INFINITY, -INFINITY, -INFINITY);
#pragma unroll 4
        for (int i = 0; i < MM_CHUNK / 8; ++i) {
            int row = i * 8 + rg;
            float4 v = img4[(size_t)sr[row] * 32 + c4];
            min4(mn, v); max4(mx, v);
        }
        int ch = c4 * 4;
        *(float4*)&red[0][rg][ch] = mn;
        *(float4*)&red[1][rg][ch] = mx;
        __syncthreads();
        if (tid < 128) {
            float m0 = red[0][0][tid], m1 = red[1][0][tid];
#pragma unroll
            for (int g = 1; g < 8; ++g) {
                m0 = fminf(m0, red[0][g][tid]);
                m1 = fmaxf(m1, red[1][g][tid]);
            }
            atomicMin(&g_kmin[128 + tid], enc_f(m0));   // b = 0
            atomicMax(&g_kmax[128 + tid], enc_f(m1));
        }
    } else if (tid < 128) {
        float mn = INFINITY, mx = -INFINITY;
        int cur = sb[0];
        for (int i = 0; i < cnt; ++i) {
            int b = sb[i];
            if (b != cur) {
                atomicMin(&g_kmin[cur * 256 + 128 + tid], enc_f(mn));
                atomicMax(&g_kmax[cur * 256 + 128 + tid], enc_f(mx));
                cur = b; mn = INFINITY; mx = -INFINITY;
            }
            float v = g_imgT[(size_t)sr[i] * C_C + tid];
            mn = fminf(mn, v); mx = fmaxf(mx, v);
        }
        atomicMin(&g_kmin[cur * 256 + 128 + tid], enc_f(mn));
        atomicMax(&g_kmax[cur * 256 + 128 + tid], enc_f(mx));
    }
}

// ---------------- kernel C: full gating MLP (one block per (net, batch)) --------
// block = (b << 1) | net.  hid -> att -> (hc if net==cam).  All per-(net,b)
// chains are independent, so the whole MLP is one launch.
__global__ void __launch_bounds__(256) mlpall_kernel(
    const float* __restrict__ Wl1, const float* __restrict__ Wc1,
    const float* __restrict__ Wl2, const float* __restrict__ Wc2,
    const float* __restrict__ Wf1)
{
    __shared__ float cat[CH_ALL];
    __shared__ float hid[CH_HID];
    __shared__ float gc[128];
    int blk = blockIdx.x;
    int net = blk & 1, b = blk >> 1;
    int tid = threadIdx.x;

    // assemble cat = [lmin, lmax, cmin, cmax]
    for (int k = tid; k < CH_ALL; k += 256) {
        int grp   = k >> 8;              // 0: lidar, 1: cam
        int ismax = (k >> 7) & 1;
        int c     = (k & 127) + grp * 128;
        unsigned key = ismax ? g_kmax[b * 256 + c] : g_kmin[b * 256 + c];
        cat[k] = dec_f(key);
    }
    __syncthreads();

    // hid = relu(cat @ W1), 170 outputs
    const float* W1 = net ? Wc1 : Wl1;
    if (tid < CH_HID) {
        float a0 = 0.f, a1 = 0.f, a2 = 0.f, a3 = 0.f;
        for (int k = 0; k < CH_ALL; k += 4) {
            a0 = fmaf(cat[k],     W1[k * CH_HID + tid],       a0);
            a1 = fmaf(cat[k + 1], W1[(k + 1) * CH_HID + tid], a1);
            a2 = fmaf(cat[k + 2], W1[(k + 2) * CH_HID + tid], a2);
            a3 = fmaf(cat[k + 3], W1[(k + 3) * CH_HID + tid], a3);
        }
        hid[tid] = fmaxf((a0 + a1) + (a2 + a3), 0.f);
    }
    __syncthreads();

    // att = sigmoid(relu(hid @ W2)), 128 outputs
    const float* W2 = net ? Wc2 : Wl2;
    if (tid < 128) {
        float a0 = 0.f, a1 = 0.f;
        for (int k = 0; k < CH_HID; k += 2) {
            a0 = fmaf(hid[k],     W2[k * 128 + tid],       a0);
            a1 = fmaf(hid[k + 1], W2[(k + 1) * 128 + tid], a1);
        }
        float v = fmaxf(a0 + a1, 0.f);
        float att = 1.f / (1.f + expf(-v));
        (net ? g_att_c : g_att_l)[b * 128 + tid] = att;
        if (net) gc[tid] = att * g_imgT[(size_t)(SPATIAL - 2) * C_C + tid];
    }
    if (net) {    // cam blocks also compute the per-batch GEMM1 bias
        __syncthreads();
        float a0 = 0.f, a1 = 0.f;
        for (int k = 0; k < 128; k += 2) {
            a0 = fmaf(gc[k],     Wf1[(128 + k) * 256 + tid], a0);
            a1 = fmaf(gc[k + 1], Wf1[(129 + k) * 256 + tid], a1);
        }
        g_hc[b * 256 + tid] = a0 + a1;
    }
}

// ---------------- B panel-0 prefetch (buf0) ---------------------------------------
__device__ __forceinline__ void preload_B0(u32 smb, const uint4* __restrict__ Bimg, int tid) {
    u32 dst = smb + SM_B + (u32)tid * 16u;
    const uint4* s = Bimg + tid;
#pragma unroll
    for (int i = 0; i < 8; ++i) cp16(dst + i * 4096u, s + i * 256);
    cp_commit();
}

// ---------------- fused GEMM stage (M=64, fp16 single-term, NP panels) -----------
template<int NP>
__device__ __forceinline__ void gemm_stage(
    u32 smb, u32 Abase, const uint4* __restrict__ Bimg,
    float acc[2][8][4], int tid, int lane, int wm, int wn)
{
    const u32 Bb = smb + SM_B;
#pragma unroll 1
    for (int p = 0; p < NP; ++p) {
        if (p < NP - 1) {
            u32 dst = Bb + (u32)((p + 1) & 1) * 32768u + (u32)tid * 16u;
            const uint4* s = Bimg + (p + 1) * 2048 + tid;
#pragma unroll
            for (int i = 0; i < 8; ++i) cp16(dst + i * 4096u, s + i * 256);
            cp_commit();
            cp_wait1();
        } else {
            cp_wait0();
        }
        __syncthreads();
        u32 B = Bb + (u32)(p & 1) * 32768u;
#pragma unroll
        for (int s = 0; s < 4; ++s) {
            int k8 = p * 8 + s * 2 + (lane >> 4);
            int arow = wm + (lane & 15);
            u32 aoff = (u32)arow * 512u + ((u32)(k8 ^ (arow & 7)) << 4);
            u32 ah[2][4];
            ldsm4(Abase + aoff,          ah[0][0], ah[0][1], ah[0][2], ah[0][3]);
            ldsm4(Abase + aoff + 8192u,  ah[1][0], ah[1][1], ah[1][2], ah[1][3]);
            int k8h = s * 2 + (lane >> 4);
            u32 bh[8][2];
#pragma unroll
            for (int j16 = 0; j16 < 4; ++j16) {
                int brow = wn + j16 * 16 + (lane & 15);
                u32 rb = B + (u32)brow * 128u;
                u32 r0, r1, r2, r3;
                ldsm4(rb + ((u32)(k8h ^ (brow & 7)) << 4), r0, r1, r2, r3);
                bh[2*j16][0] = r0;   bh[2*j16][1] = r2;
                bh[2*j16+1][0] = r1; bh[2*j16+1][1] = r3;
            }
#pragma unroll
            for (int t = 0; t < 2; ++t)
#pragma unroll
                for (int j = 0; j < 8; ++j)
                    mma16816(acc[t][j], ah[t], bh[j][0], bh[j][1]);
        }
        __syncthreads();
    }
}

// ---------------- kernel D: persistent fused gate+GEMM1+ReLU+GEMM2+ReLU ----------
__global__ void __launch_bounds__(256, 2) fused_mma_kernel(
    const float* __restrict__ lidar,
    const int* __restrict__ batch_idx,
    const int* __restrict__ y_idx,
    const int* __restrict__ x_idx,
    float* __restrict__ out, int N, int ntiles)
{
    extern __shared__ char sm[];
    const u32 smb = smem_u32(sm);
    int* sbv = (int*)(sm + SM_SB);
    const int tid  = threadIdx.x;
    const int lane = tid & 31;
    const int wid  = tid >> 5;
    const int wm   = (wid & 1) * 32;
    const int wn   = (wid >> 1) * 64;

    for (int tile = blockIdx.x; tile < ntiles; tile += gridDim.x) {
        int first_n = tile * 64;
        if (first_n >= N) first_n = N - 1;
        const bool short_tile = (batch_idx[first_n] >= 1);

        // prefetch GEMM1 B panel 0 — overlaps the phase-1 gather below.
        preload_B0(smb, (const uint4*)g_B1, tid);

        // ---- phase 1: gather + gate + fp16 cvt into A smem (swizzled) ----
        {
            int m = tid >> 2, q = tid & 3;
            int n = tile * 64 + m;
            int nn = n < N ? n : N - 1;
            int b = batch_idx[nn];
            if (q == 0) sbv[m] = b;
            if (!(short_tile && q >= 2)) {
                const float* src;
                const float* att;
                if (q < 2) { src = lidar + (size_t)nn * C_L; att = g_att_l + b * 128; }
                else {
                    int r = b * SPATIAL + y_idx[nn] * WW + x_idx[nn];
                    if (r > SPATIAL - 2) r = SPATIAL - 2;
                    src = g_imgT + (size_t)r * C_C; att = g_att_c + b * 128;
                }
                const float4* s4 = (const float4*)src;
                const float4* g4 = (const float4*)att;
                int ho = (q & 1) * 16;
                u32 rowb = (u32)m * 512u;
                u32 xm = (u32)(m & 7);
#pragma unroll
                for (int i = 0; i < 8; ++i) {
                    float4 a0 = s4[ho + 2*i], a1 = s4[ho + 2*i + 1];
                    float4 q0 = g4[ho + 2*i], q1 = g4[ho + 2*i + 1];
                    __half2 h0 = __floats2half2_rn(a0.x*q0.x, a0.y*q0.y);
                    __half2 h1 = __floats2half2_rn(a0.z*q0.z, a0.w*q0.w);
                    __half2 h2 = __floats2half2_rn(a1.x*q1.x, a1.y*q1.y);
                    __half2 h3 = __floats2half2_rn(a1.z*q1.z, a1.w*q1.w);
                    uint4 H = make_uint4(*(u32*)&h0, *(u32*)&h1, *(u32*)&h2, *(u32*)&h3);
                    u32 k8 = (u32)(q * 8 + i);
                    u32 off = rowb + ((k8 ^ xm) << 4);
                    *(uint4*)(sm + SM_AH + off) = H;
                }
            }
        }
        __syncthreads();   // sbv + A visible

        // ---- acc init: zero (full) or per-row cam bias hc[b] (short) ----
        float acc[2][8][4];
        if (short_tile) {
#pragma unroll
            for (int t = 0; t < 2; ++t) {
                int r0 = wm + 16 * t + (lane >> 2);
                int r1 = r0 + 8;
                const float* h0 = g_hc + sbv[r0] * 256;
                const float* h1 = g_hc + sbv[r1] * 256;
#pragma unroll
                for (int j = 0; j < 8; ++j) {
                    int col = wn + 8 * j + 2 * (lane & 3);
                    acc[t][j][0] = h0[col];   acc[t][j][1] = h0[col + 1];
                    acc[t][j][2] = h1[col];   acc[t][j][3] = h1[col + 1];
                }
            }
        } else {
#pragma unroll
            for (int t = 0; t < 2; ++t)
#pragma unroll
                for (int j = 0; j < 8; ++j)
#pragma unroll
                    for (int c = 0; c < 4; ++c) acc[t][j][c] = 0.f;
        }

        // ---- GEMM1: K=128 (short) or K=256 (full) ----
        if (short_tile)
            gemm_stage<2>(smb, smb + SM_AH, (const uint4*)g_B1, acc, tid, lane, wm, wn);
        else
            gemm_stage<4>(smb, smb + SM_AH, (const uint4*)g_B1, acc, tid, lane, wm, wn);

        // prefetch GEMM2 B panel 0 — overlaps epilogue 1
        preload_B0(smb, (const uint4*)g_B2, tid);

        // ---- epilogue 1: relu + fp16 cvt -> h (overwrites A smem) ----
        {
#pragma unroll
            for (int t = 0; t < 2; ++t) {
                int r0 = wm + 16 * t + (lane >> 2);
                int r1 = r0 + 8;
#pragma unroll
                for (int j = 0; j < 8; ++j) {
                    float* c = acc[t][j];
                    u32 k8 = (u32)((wn >> 3) + j);
                    u32 eb = (u32)(lane & 3) * 4u;
                    __half2 p0 = __floats2half2_rn(fmaxf(c[0], 0.f), fmaxf(c[1], 0.f));
                    __half2 p1 = __floats2half2_rn(fmaxf(c[2], 0.f), fmaxf(c[3], 0.f));
                    u32 o0 = (u32)r0 * 512u + ((k8 ^ (u32)(r0 & 7)) << 4) + eb;
                    u32 o1 = (u32)r1 * 512u + ((k8 ^ (u32)(r1 & 7)) << 4) + eb;
                    *(u32*)(sm + SM_AH + o0) = *(u32*)&p0;
                    *(u32*)(sm + SM_AH + o1) = *(u32*)&p1;
                }
            }
        }
        __syncthreads();

#pragma unroll
        for (int t = 0; t < 2; ++t)
#pragma unroll
            for (int j = 0; j < 8; ++j)
#pragma unroll
                for (int c = 0; c < 4; ++c) acc[t][j][c] = 0.f;

        // ---- GEMM2 ----
        gemm_stage<4>(smb, smb + SM_AH, (const uint4*)g_B2, acc, tid, lane, wm, wn);

        // ---- epilogue 2: relu -> gmem ----
        {
            int mbase = tile * 64;
#pragma unroll
            for (int t = 0; t < 2; ++t) {
                int r0 = mbase + wm + 16 * t + (lane >> 2);
                int r1 = r0 + 8;
#pragma unroll
                for (int j = 0; j < 8; ++j) {
                    float* c = acc[t][j];
                    int col = wn + 8 * j + 2 * (lane & 3);
                    if (r0 < N) {
                        float2 v = make_float2(fmaxf(c[0], 0.f), fmaxf(c[1], 0.f));
                        *(float2*)(out + (size_t)r0 * 256 + col) = v;
                    }
                    if (r1 < N) {
                        float2 v = make_float2(fmaxf(c[2], 0.f), fmaxf(c[3], 0.f));
                        *(float2*)(out + (size_t)r1 * 256 + col) = v;
                    }
                }
            }
        }
    }
}

// ---------------- host launcher ---------------------------------------------------
extern "C" void kernel_launch(void* const* d_in, const int* in_sizes, int n_in,
                              void* d_out, int out_size)
{
    int iL = -1, iImg = -1, iB = -1, iY = -1, iX = -1;
    int iWl1 = -1, iWl2 = -1, iWc1 = -1, iWc2 = -1, iWf1 = -1, iWf2 = -1;
    for (int i = 0; i < n_in; ++i) {
        int s = in_sizes[i];
        if      (s == BB * C_C * SPATIAL)      iImg = i;
        else if (s == CH_ALL * CH_HID)         { if (iWl1 < 0) iWl1 = i; else iWc1 = i; }
        else if (s == CH_HID * C_L)            { if (iWl2 < 0) iWl2 = i; else iWc2 = i; }
        else if (s == C_OUT * C_OUT)           { if (iWf1 < 0) iWf1 = i; else iWf2 = i; }
        else if (s % C_L == 0 && s >= 1000000) iL = i;
        else                                   { if (iB < 0) iB = i; else if (iY < 0) iY = i; else iX = i; }
    }
    const float* lidar = (const float*)d_in[iL];
    const float* img   = (const float*)d_in[iImg];
    const int*   bidx  = (const int*)d_in[iB];
    const int*   yidx  = (const int*)d_in[iY];
    const int*   xidx  = (const int*)d_in[iX];
    const float* Wl1   = (const float*)d_in[iWl1];
    const float* Wl2   = (const float*)d_in[iWl2];
    const float* Wc1   = (const float*)d_in[iWc1];
    const float* Wc2   = (const float*)d_in[iWc2];
    const float* Wf1   = (const float*)d_in[iWf1];
    const float* Wf2   = (const float*)d_in[iWf2];
    float* out = (float*)d_out;
    const int N = in_sizes[iL] / C_L;
    const int nchunks = (N + MM_CHUNK - 1) / MM_CHUNK;
    const int ntiles  = (N + 63) / 64;
    int gridf = ntiles < GRID_F ? ntiles : GRID_F;

    cudaFuncSetAttribute(fused_mma_kernel, cudaFuncAttributeMaxDynamicSharedMemorySize, SMEM_TOTAL);

    initk_kernel<<<1, 256>>>();
    prep_kernel<<<nchunks + TP_BLKS + 512, 256>>>(img, Wf1, Wf2, lidar, bidx, N, nchunks);
    camminmax_kernel<<<nchunks + 1, 256>>>(bidx, yidx, xidx, N, nchunks);
    mlpall_kernel<<<2 * BB, 256>>>(Wl1, Wc1, Wl2, Wc2, Wf1);
    fused_mma_kernel<<<gridf, 256, SMEM_TOTAL>>>(lidar, bidx, yidx, xidx, out, N, ntiles);
    (void)out_size;
}

// round 14
// speedup vs baseline: 1.1358x; 1.1358x over previous
#include <cuda_runtime.h>
#include <cuda_fp16.h>
#include <math.h>

// Problem constants (fixed-shape problem)
#define BB 4
#define HH_ 180
#define WW 180
#define SPATIAL (HH_ * WW)       // 32400
#define C_L 128
#define C_C 128
#define CH_ALL 512
#define CH_HID 170
#define C_OUT 256

typedef unsigned int u32;
typedef unsigned long long u64;

// ---- fused kernel smem map (bytes) ----
#define SM_AH 0
#define SM_B  32768
#define SM_SB 98304
#define SMEM_TOTAL 98560

#define GRID_F 304    // 2 CTAs x 152 SMs (GB300)
#define MM_CHUNK 128

// ---------------- device scratch ----------------------------------------------
__device__ __align__(16) float g_imgT[SPATIAL * C_C];     // img batch0 [pixel][chan]
// split min/max key arrays: [b][c], c: 0..127 lidar, 128..255 cam (encoded)
__device__ unsigned g_kmin[BB * 256];
__device__ unsigned g_kmax[BB * 256];
__device__ __align__(16) float g_hid[2][BB][CH_HID];
__device__ __align__(16) float g_att_l[BB * C_L];
__device__ __align__(16) float g_att_c[BB * C_C];
__device__ __align__(16) float g_hc[BB * C_OUT];          // per-batch GEMM1 cam bias
__device__ __align__(16) __half g_B1[65536];              // pre-swizzled fp16 weights
__device__ __align__(16) __half g_B2[65536];

// ---------------- helpers -------------------------------------------------------
__device__ __forceinline__ u32 smem_u32(const void* p) {
    u32 r;
    asm("{ .reg .u64 t; cvta.to.shared.u64 t, %1; cvt.u32.u64 %0, t; }" : "=r"(r) : "l"(p));
    return r;
}
__device__ __forceinline__ void cp16(u32 dst, const void* src) {
    asm volatile("cp.async.cg.shared.global [%0], [%1], 16;" :: "r"(dst), "l"(src) : "memory");
}
__device__ __forceinline__ void cp_commit() { asm volatile("cp.async.commit_group;" ::: "memory"); }
__device__ __forceinline__ void cp_wait0()  { asm volatile("cp.async.wait_group 0;" ::: "memory"); }
__device__ __forceinline__ void cp_wait1()  { asm volatile("cp.async.wait_group 1;" ::: "memory"); }

__device__ __forceinline__ void ldsm4(u32 a, u32 &r0, u32 &r1, u32 &r2, u32 &r3) {
    asm volatile("ldmatrix.sync.aligned.m8n8.x4.shared.b16 {%0,%1,%2,%3}, [%4];"
                 : "=r"(r0), "=r"(r1), "=r"(r2), "=r"(r3) : "r"(a));
}
__device__ __forceinline__ void mma16816(float* c, const u32* a, u32 b0, u32 b1) {
    asm volatile("mma.sync.aligned.m16n8k16.row.col.f32.f16.f16.f32 "
                 "{%0,%1,%2,%3}, {%4,%5,%6,%7}, {%8,%9}, {%0,%1,%2,%3};"
                 : "+f"(c[0]), "+f"(c[1]), "+f"(c[2]), "+f"(c[3])
                 : "r"(a[0]), "r"(a[1]), "r"(a[2]), "r"(a[3]), "r"(b0), "r"(b1));
}

// Order-preserving float <-> uint encoding for atomic min/max
__device__ __forceinline__ unsigned enc_f(float x) {
    unsigned u = __float_as_uint(x);
    return (u & 0x80000000u) ? ~u : (u | 0x80000000u);
}
__device__ __forceinline__ float dec_f(unsigned k) {
    unsigned u = (k & 0x80000000u) ? (k ^ 0x80000000u) : ~k;
    return __uint_as_float(u);
}
// decode cat element k (0..511) for batch b from split key arrays
__device__ __forceinline__ float cat_val(int b, int k) {
    int grp   = k >> 8;                 // 0: lidar, 1: cam
    int ismax = (k >> 7) & 1;
    int c     = (k & 127) + grp * 128;
    unsigned key = ismax ? g_kmax[b * 256 + c] : g_kmin[b * 256 + c];
    return dec_f(key);
}
__device__ __forceinline__ void min4(float4 &d, float4 v) {
    d.x = fminf(d.x, v.x); d.y = fminf(d.y, v.y);
    d.z = fminf(d.z, v.z); d.w = fminf(d.w, v.w);
}
__device__ __forceinline__ void max4(float4 &d, float4 v) {
    d.x = fmaxf(d.x, v.x); d.y = fmaxf(d.y, v.y);
    d.z = fmaxf(d.z, v.z); d.w = fmaxf(d.w, v.w);
}

// ---------------- kernel 0: init key arrays -------------------------------------
__global__ void initk_kernel() {
    for (int i = threadIdx.x; i < BB * 256; i += 256) {
        g_kmin[i] = 0xFFFFFFFFu;
        g_kmax[i] = 0x00000000u;
    }
}

// ---------------- kernel A: prep = lidar-minmax + transpose + weight_prep -------
// blocks [0, nchunks)            : lidar min/max scan (82MB, overlaps transpose)
// blocks [nchunks, +4052)        : transpose img_bev[0] [C][P] -> [P][C] (33MB)
// blocks [+512)                  : weight prep (fp16 + pre-swizzle)
#define TP_BLKS (((SPATIAL + 31) / 32) * 4)    // 1013 * 4 = 4052
__global__ void __launch_bounds__(256) prep_kernel(
    const float* __restrict__ img,
    const float* __restrict__ Wf1, const float* __restrict__ Wf2,
    const float* __restrict__ lidar, const int* __restrict__ batch_idx,
    int N, int nchunks)
{
    int blk = blockIdx.x;
    int tid = threadIdx.x;
    if (blk < nchunks) {
        // ---- lidar min/max for one 128-row chunk ----
        __shared__ int sb[MM_CHUNK];
        __shared__ float red[2][8][128];
        int n0 = blk * MM_CHUNK;
        int cnt = N - n0; if (cnt > MM_CHUNK) cnt = MM_CHUNK;
        if (cnt <= 0) return;
        if (tid < cnt) sb[tid] = batch_idx[n0 + tid];
        __syncthreads();
        if (cnt == MM_CHUNK && sb[0] == sb[MM_CHUNK - 1]) {
            int rg = tid >> 5, c4 = tid & 31;
            const float4* lid4 = (const float4*)lidar;
            float4 mn = make_float4( INFINITY,  INFINITY,  INFINITY,  INFINITY);
            float4 mx = make_float4(-INFINITY, -INFINITY, -INFINITY, -INFINITY);
#pragma unroll 4
            for (int i = 0; i < MM_CHUNK / 8; ++i) {
                int row = i * 8 + rg;
                float4 v = lid4[(size_t)(n0 + row) * 32 + c4];
                min4(mn, v); max4(mx, v);
            }
            int ch = c4 * 4;
            *(float4*)&red[0][rg][ch] = mn;
            *(float4*)&red[1][rg][ch] = mx;
            __syncthreads();
            if (tid < 128) {
                float m0 = red[0][0][tid], m1 = red[1][0][tid];
#pragma unroll
                for (int g = 1; g < 8; ++g) {
                    m0 = fminf(m0, red[0][g][tid]);
                    m1 = fmaxf(m1, red[1][g][tid]);
                }
                atomicMin(&g_kmin[sb[0] * 256 + tid], enc_f(m0));
                atomicMax(&g_kmax[sb[0] * 256 + tid], enc_f(m1));
            }
        } else if (tid < 128) {
            float mn = INFINITY, mx = -INFINITY;
            int cur = sb[0];
            for (int i = 0; i < cnt; ++i) {
                int b = sb[i];
                if (b != cur) {
                    atomicMin(&g_kmin[cur * 256 + tid], enc_f(mn));
                    atomicMax(&g_kmax[cur * 256 + tid], enc_f(mx));
                    cur = b; mn = INFINITY; mx = -INFINITY;
                }
                float v = lidar[(size_t)(n0 + i) * C_L + tid];
                mn = fminf(mn, v); mx = fmaxf(mx, v);
            }
            atomicMin(&g_kmin[cur * 256 + tid], enc_f(mn));
            atomicMax(&g_kmax[cur * 256 + tid], enc_f(mx));
        }
    } else if (blk < nchunks + TP_BLKS) {
        // ---- transpose ----
        __shared__ float tile[32][33];
        int b2 = blk - nchunks;
        int bx = b2 % 1013, by = b2 / 1013;
        int p0 = bx * 32, c0 = by * 32;
        int tx = tid & 31, ty = tid >> 5;
#pragma unroll
        for (int j = 0; j < 4; ++j) {
            int c = c0 + ty + j * 8;
            int p = p0 + tx;
            if (p < SPATIAL) tile[ty + j * 8][tx] = img[c * SPATIAL + p];
        }
        __syncthreads();
#pragma unroll
        for (int j = 0; j < 4; ++j) {
            int p = p0 + ty + j * 8;
            int c = c0 + tx;
            if (p < SPATIAL) g_imgT[p * C_C + c] = tile[tx][ty + j * 8];
        }
    } else {
        // ---- weight prep ----
        int idx = (blk - nchunks - TP_BLKS) * 256 + tid;   // 2 * 65536
        int mat = idx >> 16;
        int rem = idx & 65535;
        int k = rem >> 8;
        int n = rem & 255;
        const float* W = mat ? Wf2 : Wf1;
        __half hv = __float2half_rn(W[k * 256 + n]);
        int p = k >> 6, k8l = (k >> 3) & 7, e = k & 7;
        u32 off = (u32)p * 32768u + (u32)n * 128u + ((u32)(k8l ^ (n & 7)) << 4) + (u32)e * 2u;
        __half* wim = mat ? g_B2 : g_B1;
        *(unsigned short*)((char*)wim + off) = *(unsigned short*)&hv;
    }
}

// ---------------- kernel B: cam min/max (b=0 chunks only + const_cam) -----------
// For b>=1: every voxel gathers pixel 32398 (clamp) -> cam min=max=imgT[32398],
// handled by the extra block; chunks starting at b>=1 exit immediately.
__global__ void __launch_bounds__(256) camminmax_kernel(
    const int* __restrict__ batch_idx,
    const int* __restrict__ y_idx, const int* __restrict__ x_idx,
    int N, int nchunks)
{
    int tid = threadIdx.x;
    if ((int)blockIdx.x == nchunks) {    // const_cam block
        for (int i = tid; i < 384; i += 256) {
            int b = 1 + (i >> 7);
            int c = i & 127;
            unsigned e = enc_f(g_imgT[(size_t)(SPATIAL - 2) * C_C + c]);
            atomicMin(&g_kmin[b * 256 + 128 + c], e);
            atomicMax(&g_kmax[b * 256 + 128 + c], e);
        }
        return;
    }
    int n0 = blockIdx.x * MM_CHUNK;
    int cnt = N - n0; if (cnt > MM_CHUNK) cnt = MM_CHUNK;
    if (cnt <= 0) return;
    if (batch_idx[n0] >= 1) return;      // whole chunk b>=1 (sorted) -> constant cam

    __shared__ int sb[MM_CHUNK];
    __shared__ int sr[MM_CHUNK];
    __shared__ float red[2][8][128];
    if (tid < cnt) {
        int n = n0 + tid;
        int b = batch_idx[n];
        int r = b * SPATIAL + y_idx[n] * WW + x_idx[n];
        if (r > SPATIAL - 2) r = SPATIAL - 2;
        sb[tid] = b; sr[tid] = r;
    }
    __syncthreads();

    if (cnt == MM_CHUNK && sb[MM_CHUNK - 1] == 0) {
        int rg = tid >> 5, c4 = tid & 31;
        const float4* img4 = (const float4*)g_imgT;
        float4 mn = make_float4( INFINITY,  INFINITY,  INFINITY,  INFINITY);
        float4 mx = make_float4(-INFINITY, -INFINITY, -INFINITY, -INFINITY);
#pragma unroll 4
        for (int i = 0; i < MM_CHUNK / 8; ++i) {
            int row = i * 8 + rg;
            float4 v = img4[(size_t)sr[row] * 32 + c4];
            min4(mn, v); max4(mx, v);
        }
        int ch = c4 * 4;
        *(float4*)&red[0][rg][ch] = mn;
        *(float4*)&red[1][rg][ch] = mx;
        __syncthreads();
        if (tid < 128) {
            float m0 = red[0][0][tid], m1 = red[1][0][tid];
#pragma unroll
            for (int g = 1; g < 8; ++g) {
                m0 = fminf(m0, red[0][g][tid]);
                m1 = fmaxf(m1, red[1][g][tid]);
            }
            atomicMin(&g_kmin[128 + tid], enc_f(m0));   // b = 0
            atomicMax(&g_kmax[128 + tid], enc_f(m1));
        }
    } else if (tid < 128) {
        float mn = INFINITY, mx = -INFINITY;
        int cur = sb[0];
        for (int i = 0; i < cnt; ++i) {
            int b = sb[i];
            if (b != cur) {
                atomicMin(&g_kmin[cur * 256 + 128 + tid], enc_f(mn));
                atomicMax(&g_kmax[cur * 256 + 128 + tid], enc_f(mx));
                cur = b; mn = INFINITY; mx = -INFINITY;
            }
            float v = g_imgT[(size_t)sr[i] * C_C + tid];
            mn = fminf(mn, v); mx = fmaxf(mx, v);
        }
        atomicMin(&g_kmin[cur * 256 + 128 + tid], enc_f(mn));
        atomicMax(&g_kmax[cur * 256 + 128 + tid], enc_f(mx));
    }
}

// ---------------- kernel C: gating MLP layer 1 (warp per output) ----------------
__global__ void __launch_bounds__(256) mlp1_kernel(
    const float* __restrict__ Wl1, const float* __restrict__ Wc1)
{
    int gw   = blockIdx.x * 8 + (threadIdx.x >> 5);
    int lane = threadIdx.x & 31;
    int net  = gw / (BB * CH_HID);
    int rem  = gw % (BB * CH_HID);
    int b    = rem / CH_HID;
    int j    = rem % CH_HID;
    const float* W = net ? Wc1 : Wl1;
    float s = 0.f;
#pragma unroll
    for (int t = 0; t < 16; ++t) {
        int k = lane + 32 * t;
        s = fmaf(cat_val(b, k), W[k * CH_HID + j], s);
    }
#pragma unroll
    for (int o = 16; o; o >>= 1) s += __shfl_xor_sync(0xffffffffu, s, o);
    if (lane == 0) g_hid[net][b][j] = fmaxf(s, 0.f);
}

// ---------------- kernel D: gating MLP layer 2 + sigmoid (warp per output) ------
__global__ void __launch_bounds__(256) mlp2_kernel(
    const float* __restrict__ Wl2, const float* __restrict__ Wc2)
{
    int gw   = blockIdx.x * 8 + (threadIdx.x >> 5);   // 0..1023
    int lane = threadIdx.x & 31;
    int net  = gw >> 9, rem = gw & 511;
    int b    = rem >> 7, cc = rem & 127;
    const float* W2 = net ? Wc2 : Wl2;
    const float* h  = g_hid[net][b];
    float s = 0.f;
#pragma unroll
    for (int t = 0; t < 6; ++t) {
        int k = lane + 32 * t;
        if (k < CH_HID) s = fmaf(h[k], W2[k * 128 + cc], s);
    }
#pragma unroll
    for (int o = 16; o; o >>= 1) s += __shfl_xor_sync(0xffffffffu, s, o);
    if (lane == 0) {
        float v = fmaxf(s, 0.f);
        (net ? g_att_c : g_att_l)[b * 128 + cc] = 1.f / (1.f + expf(-v));
    }
}

// ---------------- kernel E: per-batch GEMM1 cam bias (warp per output) ----------
// hc[b][n] = sum_k (att_c[b][k] * imgT[32398][k]) * Wf1[128+k][n]
__global__ void __launch_bounds__(256) hc_kernel(const float* __restrict__ Wf1) {
    int gw   = blockIdx.x * 8 + (threadIdx.x >> 5);   // 0..1023
    int lane = threadIdx.x & 31;
    int b    = gw >> 8, n = gw & 255;
    float s = 0.f;
#pragma unroll
    for (int t = 0; t < 4; ++t) {
        int k = lane + 32 * t;
        float gc = g_att_c[b * 128 + k] * g_imgT[(size_t)(SPATIAL - 2) * C_C + k];
        s = fmaf(gc, Wf1[(128 + k) * 256 + n], s);
    }
#pragma unroll
    for (int o = 16; o; o >>= 1) s += __shfl_xor_sync(0xffffffffu, s, o);
    if (lane == 0) g_hc[b * 256 + n] = s;
}

// ---------------- B panel-0 prefetch (buf0) ---------------------------------------
__device__ __forceinline__ void preload_B0(u32 smb, const uint4* __restrict__ Bimg, int tid) {
    u32 dst = smb + SM_B + (u32)tid * 16u;
    const uint4* s = Bimg + tid;
#pragma unroll
    for (int i = 0; i < 8; ++i) cp16(dst + i * 4096u, s + i * 256);
    cp_commit();
}

// ---------------- fused GEMM stage (M=64, fp16 single-term, NP panels) -----------
// Panel 0 must already be prefetched into buf0 (one pending commit group).
template<int NP>
__device__ __forceinline__ void gemm_stage(
    u32 smb, u32 Abase, const uint4* __restrict__ Bimg,
    float acc[2][8][4], int tid, int lane, int wm, int wn)
{
    const u32 Bb = smb + SM_B;
#pragma unroll 1
    for (int p = 0; p < NP; ++p) {
        if (p < NP - 1) {
            u32 dst = Bb + (u32)((p + 1) & 1) * 32768u + (u32)tid * 16u;
            const uint4* s = Bimg + (p + 1) * 2048 + tid;
#pragma unroll
            for (int i = 0; i < 8; ++i) cp16(dst + i * 4096u, s + i * 256);
            cp_commit();
            cp_wait1();
        } else {
            cp_wait0();
        }
        __syncthreads();
        u32 B = Bb + (u32)(p & 1) * 32768u;
#pragma unroll
        for (int s = 0; s < 4; ++s) {
            int k8 = p * 8 + s * 2 + (lane >> 4);
            int arow = wm + (lane & 15);
            u32 aoff = (u32)arow * 512u + ((u32)(k8 ^ (arow & 7)) << 4);
            u32 ah[2][4];
            ldsm4(Abase + aoff,          ah[0][0], ah[0][1], ah[0][2], ah[0][3]);
            ldsm4(Abase + aoff + 8192u,  ah[1][0], ah[1][1], ah[1][2], ah[1][3]);
            int k8h = s * 2 + (lane >> 4);
            u32 bh[8][2];
#pragma unroll
            for (int j16 = 0; j16 < 4; ++j16) {
                int brow = wn + j16 * 16 + (lane & 15);
                u32 rb = B + (u32)brow * 128u;
                u32 r0, r1, r2, r3;
                ldsm4(rb + ((u32)(k8h ^ (brow & 7)) << 4), r0, r1, r2, r3);
                bh[2*j16][0] = r0;   bh[2*j16][1] = r2;
                bh[2*j16+1][0] = r1; bh[2*j16+1][1] = r3;
            }
#pragma unroll
            for (int t = 0; t < 2; ++t)
#pragma unroll
                for (int j = 0; j < 8; ++j)
                    mma16816(acc[t][j], ah[t], bh[j][0], bh[j][1]);
        }
        __syncthreads();
    }
}

// ---------------- kernel F: persistent fused gate+GEMM1+ReLU+GEMM2+ReLU ----------
__global__ void __launch_bounds__(256, 2) fused_mma_kernel(
    const float* __restrict__ lidar,
    const int* __restrict__ batch_idx,
    const int* __restrict__ y_idx,
    const int* __restrict__ x_idx,
    float* __restrict__ out, int N, int ntiles)
{
    extern __shared__ char sm[];
    const u32 smb = smem_u32(sm);
    int* sbv = (int*)(sm + SM_SB);
    const int tid  = threadIdx.x;
    const int lane = tid & 31;
    const int wid  = tid >> 5;
    const int wm   = (wid & 1) * 32;
    const int wn   = (wid >> 1) * 64;

    for (int tile = blockIdx.x; tile < ntiles; tile += gridDim.x) {
        int first_n = tile * 64;
        if (first_n >= N) first_n = N - 1;
        const bool short_tile = (batch_idx[first_n] >= 1);

        // prefetch GEMM1 B panel 0 — overlaps the phase-1 gather below.
        preload_B0(smb, (const uint4*)g_B1, tid);

        // ---- phase 1: gather + gate + fp16 cvt into A smem (swizzled) ----
        {
            int m = tid >> 2, q = tid & 3;
            int n = tile * 64 + m;
            int nn = n < N ? n : N - 1;
            int b = batch_idx[nn];
            if (q == 0) sbv[m] = b;
            if (!(short_tile && q >= 2)) {
                const float* src;
                const float* att;
                if (q < 2) { src = lidar + (size_t)nn * C_L; att = g_att_l + b * 128; }
                else {
                    int r = b * SPATIAL + y_idx[nn] * WW + x_idx[nn];
                    if (r > SPATIAL - 2) r = SPATIAL - 2;
                    src = g_imgT + (size_t)r * C_C; att = g_att_c + b * 128;
                }
                const float4* s4 = (const float4*)src;
                const float4* g4 = (const float4*)att;
                int ho = (q & 1) * 16;
                u32 rowb = (u32)m * 512u;
                u32 xm = (u32)(m & 7);
#pragma unroll
                for (int i = 0; i < 8; ++i) {
                    float4 a0 = s4[ho + 2*i], a1 = s4[ho + 2*i + 1];
                    float4 q0 = g4[ho + 2*i], q1 = g4[ho + 2*i + 1];
                    __half2 h0 = __floats2half2_rn(a0.x*q0.x, a0.y*q0.y);
                    __half2 h1 = __floats2half2_rn(a0.z*q0.z, a0.w*q0.w);
                    __half2 h2 = __floats2half2_rn(a1.x*q1.x, a1.y*q1.y);
                    __half2 h3 = __floats2half2_rn(a1.z*q1.z, a1.w*q1.w);
                    uint4 H = make_uint4(*(u32*)&h0, *(u32*)&h1, *(u32*)&h2, *(u32*)&h3);
                    u32 k8 = (u32)(q * 8 + i);
                    u32 off = rowb + ((k8 ^ xm) << 4);
                    *(uint4*)(sm + SM_AH + off) = H;
                }
            }
        }
        __syncthreads();   // sbv + A visible

        // ---- acc init: zero (full) or per-row cam bias hc[b] (short) ----
        float acc[2][8][4];
        if (short_tile) {
#pragma unroll
            for (int t = 0; t < 2; ++t) {
                int r0 = wm + 16 * t + (lane >> 2);
                int r1 = r0 + 8;
                const float* h0 = g_hc + sbv[r0] * 256;
                const float* h1 = g_hc + sbv[r1] * 256;
#pragma unroll
                for (int j = 0; j < 8; ++j) {
                    int col = wn + 8 * j + 2 * (lane & 3);
                    acc[t][j][0] = h0[col];   acc[t][j][1] = h0[col + 1];
                    acc[t][j][2] = h1[col];   acc[t][j][3] = h1[col + 1];
                }
            }
        } else {
#pragma unroll
            for (int t = 0; t < 2; ++t)
#pragma unroll
                for (int j = 0; j < 8; ++j)
#pragma unroll
                    for (int c = 0; c < 4; ++c) acc[t][j][c] = 0.f;
        }

        // ---- GEMM1: K=128 (short) or K=256 (full) ----
        if (short_tile)
            gemm_stage<2>(smb, smb + SM_AH, (const uint4*)g_B1, acc, tid, lane, wm, wn);
        else
            gemm_stage<4>(smb, smb + SM_AH, (const uint4*)g_B1, acc, tid, lane, wm, wn);

        // prefetch GEMM2 B panel 0 — overlaps epilogue 1
        preload_B0(smb, (const uint4*)g_B2, tid);

        // ---- epilogue 1: relu + fp16 cvt -> h (overwrites A smem) ----
        {
#pragma unroll
            for (int t = 0; t < 2; ++t) {
                int r0 = wm + 16 * t + (lane >> 2);
                int r1 = r0 + 8;
#pragma unroll
                for (int j = 0; j < 8; ++j) {
                    float* c = acc[t][j];
                    u32 k8 = (u32)((wn >> 3) + j);
                    u32 eb = (u32)(lane & 3) * 4u;
                    __half2 p0 = __floats2half2_rn(fmaxf(c[0], 0.f), fmaxf(c[1], 0.f));
                    __half2 p1 = __floats2half2_rn(fmaxf(c[2], 0.f), fmaxf(c[3], 0.f));
                    u32 o0 = (u32)r0 * 512u + ((k8 ^ (u32)(r0 & 7)) << 4) + eb;
                    u32 o1 = (u32)r1 * 512u + ((k8 ^ (u32)(r1 & 7)) << 4) + eb;
                    *(u32*)(sm + SM_AH + o0) = *(u32*)&p0;
                    *(u32*)(sm + SM_AH + o1) = *(u32*)&p1;
                }
            }
        }
        __syncthreads();

#pragma unroll
        for (int t = 0; t < 2; ++t)
#pragma unroll
            for (int j = 0; j < 8; ++j)
#pragma unroll
                for (int c = 0; c < 4; ++c) acc[t][j][c] = 0.f;

        // ---- GEMM2 ----
        gemm_stage<4>(smb, smb + SM_AH, (const uint4*)g_B2, acc, tid, lane, wm, wn);

        // ---- epilogue 2: relu -> gmem ----
        {
            int mbase = tile * 64;
#pragma unroll
            for (int t = 0; t < 2; ++t) {
                int r0 = mbase + wm + 16 * t + (lane >> 2);
                int r1 = r0 + 8;
#pragma unroll
                for (int j = 0; j < 8; ++j) {
                    float* c = acc[t][j];
                    int col = wn + 8 * j + 2 * (lane & 3);
                    if (r0 < N) {
                        float2 v = make_float2(fmaxf(c[0], 0.f), fmaxf(c[1], 0.f));
                        *(float2*)(out + (size_t)r0 * 256 + col) = v;
                    }
                    if (r1 < N) {
                        float2 v = make_float2(fmaxf(c[2], 0.f), fmaxf(c[3], 0.f));
                        *(float2*)(out + (size_t)r1 * 256 + col) = v;
                    }
                }
            }
        }
    }
}

// ---------------- host launcher ---------------------------------------------------
extern "C" void kernel_launch(void* const* d_in, const int* in_sizes, int n_in,
                              void* d_out, int out_size)
{
    int iL = -1, iImg = -1, iB = -1, iY = -1, iX = -1;
    int iWl1 = -1, iWl2 = -1, iWc1 = -1, iWc2 = -1, iWf1 = -1, iWf2 = -1;
    for (int i = 0; i < n_in; ++i) {
        int s = in_sizes[i];
        if      (s == BB * C_C * SPATIAL)      iImg = i;
        else if (s == CH_ALL * CH_HID)         { if (iWl1 < 0) iWl1 = i; else iWc1 = i; }
        else if (s == CH_HID * C_L)            { if (iWl2 < 0) iWl2 = i; else iWc2 = i; }
        else if (s == C_OUT * C_OUT)           { if (iWf1 < 0) iWf1 = i; else iWf2 = i; }
        else if (s % C_L == 0 && s >= 1000000) iL = i;
        else                                   { if (iB < 0) iB = i; else if (iY < 0) iY = i; else iX = i; }
    }
    const float* lidar = (const float*)d_in[iL];
    const float* img   = (const float*)d_in[iImg];
    const int*   bidx  = (const int*)d_in[iB];
    const int*   yidx  = (const int*)d_in[iY];
    const int*   xidx  = (const int*)d_in[iX];
    const float* Wl1   = (const float*)d_in[iWl1];
    const float* Wl2   = (const float*)d_in[iWl2];
    const float* Wc1   = (const float*)d_in[iWc1];
    const float* Wc2   = (const float*)d_in[iWc2];
    const float* Wf1   = (const float*)d_in[iWf1];
    const float* Wf2   = (const float*)d_in[iWf2];
    float* out = (float*)d_out;
    const int N = in_sizes[iL] / C_L;
    const int nchunks = (N + MM_CHUNK - 1) / MM_CHUNK;
    const int ntiles  = (N + 63) / 64;
    int gridf = ntiles < GRID_F ? ntiles : GRID_F;

    cudaFuncSetAttribute(fused_mma_kernel, cudaFuncAttributeMaxDynamicSharedMemorySize, SMEM_TOTAL);

    initk_kernel<<<1, 256>>>();
    prep_kernel<<<nchunks + TP_BLKS + 512, 256>>>(img, Wf1, Wf2, lidar, bidx, N, nchunks);
    camminmax_kernel<<<nchunks + 1, 256>>>(bidx, yidx, xidx, N, nchunks);
    mlp1_kernel<<<CH_HID, 256>>>(Wl1, Wc1);
    mlp2_kernel<<<128, 256>>>(Wl2, Wc2);
    hc_kernel<<<128, 256>>>(Wf1);
    fused_mma_kernel<<<gridf, 256, SMEM_TOTAL>>>(lidar, bidx, yidx, xidx, out, N, ntiles);
    (void)out_size;
}

// round 15
// speedup vs baseline: 1.1818x; 1.0405x over previous
#include <cuda_runtime.h>
#include <cuda_fp16.h>
#include <math.h>

// Problem constants (fixed-shape problem)
#define BB 4
#define HH_ 180
#define WW 180
#define SPATIAL (HH_ * WW)       // 32400
#define C_L 128
#define C_C 128
#define CH_ALL 512
#define CH_HID 170
#define C_OUT 256

typedef unsigned int u32;
typedef unsigned long long u64;

// ---- fused kernel smem map (bytes) ----
#define SM_AH 0
#define SM_B  32768
#define SM_SB 98304
#define SMEM_TOTAL 98560

#define GRID_F 304    // 2 CTAs x 152 SMs (GB300)
#define MM_CHUNK 128

// ---------------- device scratch ----------------------------------------------
__device__ __align__(16) float g_imgT[SPATIAL * C_C];     // img batch0 [pixel][chan]
__device__ unsigned g_keys[BB * CH_ALL];                  // encoded min/max keys
__device__ __align__(16) float g_hid[2][BB][CH_HID];
__device__ __align__(16) float g_att_l[BB * C_L];
__device__ __align__(16) float g_att_c[BB * C_C];
__device__ __align__(16) float g_hc[BB * C_OUT];          // per-batch GEMM1 cam bias
__device__ __align__(16) __half g_B1[65536];              // pre-swizzled fp16 weights
__device__ __align__(16) __half g_B2[65536];

// ---------------- helpers -------------------------------------------------------
__device__ __forceinline__ u32 smem_u32(const void* p) {
    u32 r;
    asm("{ .reg .u64 t; cvta.to.shared.u64 t, %1; cvt.u32.u64 %0, t; }" : "=r"(r) : "l"(p));
    return r;
}
__device__ __forceinline__ void cp16(u32 dst, const void* src) {
    asm volatile("cp.async.cg.shared.global [%0], [%1], 16;" :: "r"(dst), "l"(src) : "memory");
}
__device__ __forceinline__ void cp_commit() { asm volatile("cp.async.commit_group;" ::: "memory"); }
__device__ __forceinline__ void cp_wait0()  { asm volatile("cp.async.wait_group 0;" ::: "memory"); }

__device__ __forceinline__ void ldsm4(u32 a, u32 &r0, u32 &r1, u32 &r2, u32 &r3) {
    asm volatile("ldmatrix.sync.aligned.m8n8.x4.shared.b16 {%0,%1,%2,%3}, [%4];"
                 : "=r"(r0), "=r"(r1), "=r"(r2), "=r"(r3) : "r"(a));
}
__device__ __forceinline__ void mma16816(float* c, const u32* a, u32 b0, u32 b1) {
    asm volatile("mma.sync.aligned.m16n8k16.row.col.f32.f16.f16.f32 "
                 "{%0,%1,%2,%3}, {%4,%5,%6,%7}, {%8,%9}, {%0,%1,%2,%3};"
                 : "+f"(c[0]), "+f"(c[1]), "+f"(c[2]), "+f"(c[3])
                 : "r"(a[0]), "r"(a[1]), "r"(a[2]), "r"(a[3]), "r"(b0), "r"(b1));
}

// Order-preserving float <-> uint encoding for atomic min/max
__device__ __forceinline__ unsigned enc_f(float x) {
    unsigned u = __float_as_uint(x);
    return (u & 0x80000000u) ? ~u : (u | 0x80000000u);
}
__device__ __forceinline__ float dec_f(unsigned k) {
    unsigned u = (k & 0x80000000u) ? (k ^ 0x80000000u) : ~k;
    return __uint_as_float(u);
}
__device__ __forceinline__ void min4(float4 &d, float4 v) {
    d.x = fminf(d.x, v.x); d.y = fminf(d.y, v.y);
    d.z = fminf(d.z, v.z); d.w = fminf(d.w, v.w);
}
__device__ __forceinline__ void max4(float4 &d, float4 v) {
    d.x = fmaxf(d.x, v.x); d.y = fmaxf(d.y, v.y);
    d.z = fmaxf(d.z, v.z); d.w = fmaxf(d.w, v.w);
}

// ---------------- kernel A: prep = transpose + weight_prep + init_keys ----------
#define TP_BLKS (((SPATIAL + 31) / 32) * 4)    // 1013 * 4 = 4052
__global__ void __launch_bounds__(256) prep_kernel(
    const float* __restrict__ img,
    const float* __restrict__ Wf1, const float* __restrict__ Wf2)
{
    int blk = blockIdx.x;
    int tid = threadIdx.x;
    if (blk < TP_BLKS) {
        __shared__ float tile[32][33];
        int bx = blk % 1013, by = blk / 1013;
        int p0 = bx * 32, c0 = by * 32;
        int tx = tid & 31, ty = tid >> 5;
#pragma unroll
        for (int j = 0; j < 4; ++j) {
            int c = c0 + ty + j * 8;
            int p = p0 + tx;
            if (p < SPATIAL) tile[ty + j * 8][tx] = img[c * SPATIAL + p];
        }
        __syncthreads();
#pragma unroll
        for (int j = 0; j < 4; ++j) {
            int p = p0 + ty + j * 8;
            int c = c0 + tx;
            if (p < SPATIAL) g_imgT[p * C_C + c] = tile[tx][ty + j * 8];
        }
    } else if (blk < TP_BLKS + 512) {
        int idx = (blk - TP_BLKS) * 256 + tid;   // 2 * 65536
        int mat = idx >> 16;
        int rem = idx & 65535;
        int k = rem >> 8;
        int n = rem & 255;
        const float* W = mat ? Wf2 : Wf1;
        __half hv = __float2half_rn(W[k * 256 + n]);
        int p = k >> 6, k8l = (k >> 3) & 7, e = k & 7;
        u32 off = (u32)p * 32768u + (u32)n * 128u + ((u32)(k8l ^ (n & 7)) << 4) + (u32)e * 2u;
        __half* wim = mat ? g_B2 : g_B1;
        *(unsigned short*)((char*)wim + off) = *(unsigned short*)&hv;
    } else {
        int i = (blk - TP_BLKS - 512) * 256 + tid;
        if (i < BB * CH_ALL) {
            int slot = i & (CH_ALL - 1);
            bool is_min = (slot < 128) || (slot >= 256 && slot < 384);
            g_keys[i] = is_min ? 0xFFFFFFFFu : 0x00000000u;
        }
    }
}

// ---------------- kernel B: minmax (+const_cam in the extra block) --------------
__device__ __forceinline__ void flush_mm(int b, int c, float mn, float mx) {
    int msl, xsl;
    if (c < 128) { msl = c;             xsl = 128 + c; }
    else         { msl = 256 + c - 128; xsl = 384 + c - 128; }
    atomicMin(&g_keys[b * CH_ALL + msl], enc_f(mn));
    atomicMax(&g_keys[b * CH_ALL + xsl], enc_f(mx));
}
__global__ void __launch_bounds__(256) minmax_kernel(
    const float* __restrict__ lidar, const int* __restrict__ batch_idx,
    const int* __restrict__ y_idx, const int* __restrict__ x_idx,
    int N, int nchunks)
{
    int tid = threadIdx.x;
    if ((int)blockIdx.x == nchunks) {    // const_cam block (b>=1 gathers pixel 32398)
        for (int i = tid; i < 384; i += 256) {
            int b = 1 + (i >> 7);
            int c = i & 127;
            unsigned e = enc_f(g_imgT[(size_t)(SPATIAL - 2) * C_C + c]);
            atomicMin(&g_keys[b * CH_ALL + 256 + c], e);
            atomicMax(&g_keys[b * CH_ALL + 384 + c], e);
        }
        return;
    }
    __shared__ int sb[MM_CHUNK];
    __shared__ int sr[MM_CHUNK];
    __shared__ float red[4][8][128];
    int n0 = blockIdx.x * MM_CHUNK;
    int cnt = N - n0; if (cnt > MM_CHUNK) cnt = MM_CHUNK;
    if (cnt <= 0) return;
    if (tid < cnt) {
        int n = n0 + tid;
        int b = batch_idx[n];
        int r = b * SPATIAL + y_idx[n] * WW + x_idx[n];
        if (r > SPATIAL - 2) r = SPATIAL - 2;
        sb[tid] = b; sr[tid] = r;
    }
    __syncthreads();

    if (cnt == MM_CHUNK && sb[0] == sb[MM_CHUNK - 1]) {
        const int rg = tid >> 5;
        const int c4 = tid & 31;
        const float4* lid4 = (const float4*)lidar;
        const bool do_cam = (sb[0] == 0);   // cam is constant for b>=1
        float4 mnl = make_float4( INFINITY,  INFINITY,  INFINITY,  INFINITY);
        float4 mxl = make_float4(-INFINITY, -INFINITY, -INFINITY, -INFINITY);
        float4 mnc = mnl, mxc = mxl;
        if (do_cam) {
            const float4* img4 = (const float4*)g_imgT;
#pragma unroll 8
            for (int i = 0; i < MM_CHUNK / 8; ++i) {
                int row = i * 8 + rg;
                float4 lv = lid4[(size_t)(n0 + row) * 32 + c4];
                float4 cv = img4[(size_t)sr[row] * 32 + c4];
                min4(mnl, lv); max4(mxl, lv);
                min4(mnc, cv); max4(mxc, cv);
            }
        } else {
#pragma unroll 8
            for (int i = 0; i < MM_CHUNK / 8; ++i) {
                int row = i * 8 + rg;
                float4 lv = lid4[(size_t)(n0 + row) * 32 + c4];
                min4(mnl, lv); max4(mxl, lv);
            }
        }
        int ch = c4 * 4;
        *(float4*)&red[0][rg][ch] = mnl;
        *(float4*)&red[1][rg][ch] = mxl;
        if (do_cam) {
            *(float4*)&red[2][rg][ch] = mnc;
            *(float4*)&red[3][rg][ch] = mxc;
        }
        __syncthreads();
        int c = tid;
        if (c < 128 || do_cam) {
            int qm = (c < 128) ? 0 : 2;
            int cc = c & 127;
            float mn = red[qm][0][cc], mx = red[qm + 1][0][cc];
#pragma unroll
            for (int g = 1; g < 8; ++g) {
                mn = fminf(mn, red[qm][g][cc]);
                mx = fmaxf(mx, red[qm + 1][g][cc]);
            }
            flush_mm(sb[0], c, mn, mx);
        }
    } else {
        const int c = tid & 255;
        if (tid < 256) {
            const bool cam = (c >= 128);
            const float* base = cam ? (g_imgT + (c - 128)) : (lidar + c);
            float mn = INFINITY, mx = -INFINITY;
            int cur = sb[0];
            for (int i = 0; i < cnt; ++i) {
                int b = sb[i];
                if (b != cur) { flush_mm(cur, c, mn, mx); cur = b; mn = INFINITY; mx = -INFINITY; }
                float v = cam ? base[(size_t)sr[i] * C_C] : base[(size_t)(n0 + i) * C_L];
                mn = fminf(mn, v); mx = fmaxf(mx, v);
            }
            flush_mm(cur, c, mn, mx);
        }
    }
}

// ---------------- kernel C: gating MLP layer 1 (warp per output) ----------------
__global__ void __launch_bounds__(256) mlp1_kernel(
    const float* __restrict__ Wl1, const float* __restrict__ Wc1)
{
    int gw   = blockIdx.x * 8 + (threadIdx.x >> 5);
    int lane = threadIdx.x & 31;
    int net  = gw / (BB * CH_HID);
    int rem  = gw % (BB * CH_HID);
    int b    = rem / CH_HID;
    int j    = rem % CH_HID;
    const float* W = net ? Wc1 : Wl1;
    float s = 0.f;
#pragma unroll
    for (int t = 0; t < 16; ++t) {
        int k = lane + 32 * t;
        s = fmaf(dec_f(g_keys[b * CH_ALL + k]), W[k * CH_HID + j], s);
    }
#pragma unroll
    for (int o = 16; o; o >>= 1) s += __shfl_xor_sync(0xffffffffu, s, o);
    if (lane == 0) g_hid[net][b][j] = fmaxf(s, 0.f);
}

// ---------------- kernel D: gating MLP layer 2 + sigmoid (warp per output) ------
__global__ void __launch_bounds__(256) mlp2_kernel(
    const float* __restrict__ Wl2, const float* __restrict__ Wc2)
{
    int gw   = blockIdx.x * 8 + (threadIdx.x >> 5);   // 0..1023
    int lane = threadIdx.x & 31;
    int net  = gw >> 9, rem = gw & 511;
    int b    = rem >> 7, cc = rem & 127;
    const float* W2 = net ? Wc2 : Wl2;
    const float* h  = g_hid[net][b];
    float s = 0.f;
#pragma unroll
    for (int t = 0; t < 6; ++t) {
        int k = lane + 32 * t;
        if (k < CH_HID) s = fmaf(h[k], W2[k * 128 + cc], s);
    }
#pragma unroll
    for (int o = 16; o; o >>= 1) s += __shfl_xor_sync(0xffffffffu, s, o);
    if (lane == 0) {
        float v = fmaxf(s, 0.f);
        (net ? g_att_c : g_att_l)[b * 128 + cc] = 1.f / (1.f + expf(-v));
    }
}

// ---------------- kernel E: per-batch GEMM1 cam bias (warp per output) ----------
__global__ void __launch_bounds__(256) hc_kernel(const float* __restrict__ Wf1) {
    int gw   = blockIdx.x * 8 + (threadIdx.x >> 5);   // 0..1023
    int lane = threadIdx.x & 31;
    int b    = gw >> 8, n = gw & 255;
    float s = 0.f;
#pragma unroll
    for (int t = 0; t < 4; ++t) {
        int k = lane + 32 * t;
        float gc = g_att_c[b * 128 + k] * g_imgT[(size_t)(SPATIAL - 2) * C_C + k];
        s = fmaf(gc, Wf1[(128 + k) * 256 + n], s);
    }
#pragma unroll
    for (int o = 16; o; o >>= 1) s += __shfl_xor_sync(0xffffffffu, s, o);
    if (lane == 0) g_hc[b * 256 + n] = s;
}

// ---------------- B panel-0 prefetch (buf0) ---------------------------------------
__device__ __forceinline__ void preload_B0(u32 smb, const uint4* __restrict__ Bimg, int tid) {
    u32 dst = smb + SM_B + (u32)tid * 16u;
    const uint4* s = Bimg + tid;
#pragma unroll
    for (int i = 0; i < 8; ++i) cp16(dst + i * 4096u, s + i * 256);
    cp_commit();
}

// ---------------- fused GEMM stage (M=64, fp16 single-term, NP panels) -----------
// Panel 0 must already be prefetched into buf0 (one pending commit group).
// One __syncthreads per panel: [wait; sync; issue-next; compute].  The sync both
// publishes the arrived cp.async data and guarantees all warps exited the previous
// panel's compute before the next cp overwrites that buffer.  NO trailing sync —
// caller must __syncthreads() before reusing A or B smem.
template<int NP>
__device__ __forceinline__ void gemm_stage(
    u32 smb, u32 Abase, const uint4* __restrict__ Bimg,
    float acc[2][8][4], int tid, int lane, int wm, int wn)
{
    const u32 Bb = smb + SM_B;
#pragma unroll 1
    for (int p = 0; p < NP; ++p) {
        cp_wait0();
        __syncthreads();
        if (p < NP - 1) {
            u32 dst = Bb + (u32)((p + 1) & 1) * 32768u + (u32)tid * 16u;
            const uint4* s = Bimg + (p + 1) * 2048 + tid;
#pragma unroll
            for (int i = 0; i < 8; ++i) cp16(dst + i * 4096u, s + i * 256);
            cp_commit();
        }
        u32 B = Bb + (u32)(p & 1) * 32768u;
#pragma unroll
        for (int s = 0; s < 4; ++s) {
            int k8 = p * 8 + s * 2 + (lane >> 4);
            int arow = wm + (lane & 15);
            u32 aoff = (u32)arow * 512u + ((u32)(k8 ^ (arow & 7)) << 4);
            u32 ah[2][4];
            ldsm4(Abase + aoff,          ah[0][0], ah[0][1], ah[0][2], ah[0][3]);
            ldsm4(Abase + aoff + 8192u,  ah[1][0], ah[1][1], ah[1][2], ah[1][3]);
            int k8h = s * 2 + (lane >> 4);
            u32 bh[8][2];
#pragma unroll
            for (int j16 = 0; j16 < 4; ++j16) {
                int brow = wn + j16 * 16 + (lane & 15);
                u32 rb = B + (u32)brow * 128u;
                u32 r0, r1, r2, r3;
                ldsm4(rb + ((u32)(k8h ^ (brow & 7)) << 4), r0, r1, r2, r3);
                bh[2*j16][0] = r0;   bh[2*j16][1] = r2;
                bh[2*j16+1][0] = r1; bh[2*j16+1][1] = r3;
            }
#pragma unroll
            for (int t = 0; t < 2; ++t)
#pragma unroll
                for (int j = 0; j < 8; ++j)
                    mma16816(acc[t][j], ah[t], bh[j][0], bh[j][1]);
        }
    }
}

// ---------------- kernel F: persistent fused gate+GEMM1+ReLU+GEMM2+ReLU ----------
__global__ void __launch_bounds__(256, 2) fused_mma_kernel(
    const float* __restrict__ lidar,
    const int* __restrict__ batch_idx,
    const int* __restrict__ y_idx,
    const int* __restrict__ x_idx,
    float* __restrict__ out, int N, int ntiles)
{
    extern __shared__ char sm[];
    const u32 smb = smem_u32(sm);
    int* sbv = (int*)(sm + SM_SB);
    const int tid  = threadIdx.x;
    const int lane = tid & 31;
    const int wid  = tid >> 5;
    const int wm   = (wid & 1) * 32;
    const int wn   = (wid >> 1) * 64;

    for (int tile = blockIdx.x; tile < ntiles; tile += gridDim.x) {
        int first_n = tile * 64;
        if (first_n >= N) first_n = N - 1;
        const bool short_tile = (batch_idx[first_n] >= 1);

        // prefetch GEMM1 B panel 0 — overlaps the phase-1 gather below.
        // (end-of-tile sync guarantees buf0's prior readers are done)
        preload_B0(smb, (const uint4*)g_B1, tid);

        // ---- phase 1: gather + gate + fp16 cvt into A smem (swizzled) ----
        {
            int m = tid >> 2, q = tid & 3;
            int n = tile * 64 + m;
            int nn = n < N ? n : N - 1;
            int b = batch_idx[nn];
            if (q == 0) sbv[m] = b;
            if (!(short_tile && q >= 2)) {
                const float* src;
                const float* att;
                if (q < 2) { src = lidar + (size_t)nn * C_L; att = g_att_l + b * 128; }
                else {
                    int r = b * SPATIAL + y_idx[nn] * WW + x_idx[nn];
                    if (r > SPATIAL - 2) r = SPATIAL - 2;
                    src = g_imgT + (size_t)r * C_C; att = g_att_c + b * 128;
                }
                const float4* s4 = (const float4*)src;
                const float4* g4 = (const float4*)att;
                int ho = (q & 1) * 16;
                u32 rowb = (u32)m * 512u;
                u32 xm = (u32)(m & 7);
#pragma unroll
                for (int i = 0; i < 8; ++i) {
                    float4 a0 = s4[ho + 2*i], a1 = s4[ho + 2*i + 1];
                    float4 q0 = g4[ho + 2*i], q1 = g4[ho + 2*i + 1];
                    __half2 h0 = __floats2half2_rn(a0.x*q0.x, a0.y*q0.y);
                    __half2 h1 = __floats2half2_rn(a0.z*q0.z, a0.w*q0.w);
                    __half2 h2 = __floats2half2_rn(a1.x*q1.x, a1.y*q1.y);
                    __half2 h3 = __floats2half2_rn(a1.z*q1.z, a1.w*q1.w);
                    uint4 H = make_uint4(*(u32*)&h0, *(u32*)&h1, *(u32*)&h2, *(u32*)&h3);
                    u32 k8 = (u32)(q * 8 + i);
                    u32 off = rowb + ((k8 ^ xm) << 4);
                    *(uint4*)(sm + SM_AH + off) = H;
                }
            }
        }
        __syncthreads();   // sbv + A visible (acc init below reads sbv)

        // ---- acc init: zero (full) or per-row cam bias hc[b] (short) ----
        float acc[2][8][4];
        if (short_tile) {
#pragma unroll
            for (int t = 0; t < 2; ++t) {
                int r0 = wm + 16 * t + (lane >> 2);
                int r1 = r0 + 8;
                const float* h0 = g_hc + sbv[r0] * 256;
                const float* h1 = g_hc + sbv[r1] * 256;
#pragma unroll
                for (int j = 0; j < 8; ++j) {
                    int col = wn + 8 * j + 2 * (lane & 3);
                    acc[t][j][0] = h0[col];   acc[t][j][1] = h0[col + 1];
                    acc[t][j][2] = h1[col];   acc[t][j][3] = h1[col + 1];
                }
            }
        } else {
#pragma unroll
            for (int t = 0; t < 2; ++t)
#pragma unroll
                for (int j = 0; j < 8; ++j)
#pragma unroll
                    for (int c = 0; c < 4; ++c) acc[t][j][c] = 0.f;
        }

        // ---- GEMM1: K=128 (short) or K=256 (full) ----
        if (short_tile)
            gemm_stage<2>(smb, smb + SM_AH, (const uint4*)g_B1, acc, tid, lane, wm, wn);
        else
            gemm_stage<4>(smb, smb + SM_AH, (const uint4*)g_B1, acc, tid, lane, wm, wn);
        __syncthreads();   // all GEMM1 A/B reads complete

        // prefetch GEMM2 B panel 0 — overlaps epilogue 1
        preload_B0(smb, (const uint4*)g_B2, tid);

        // ---- epilogue 1: relu + fp16 cvt -> h (overwrites A smem; safe after sync;
        //      GEMM2's first in-loop sync publishes these writes before ldsm) ----
        {
#pragma unroll
            for (int t = 0; t < 2; ++t) {
                int r0 = wm + 16 * t + (lane >> 2);
                int r1 = r0 + 8;
#pragma unroll
                for (int j = 0; j < 8; ++j) {
                    float* c = acc[t][j];
                    u32 k8 = (u32)((wn >> 3) + j);
                    u32 eb = (u32)(lane & 3) * 4u;
                    __half2 p0 = __floats2half2_rn(fmaxf(c[0], 0.f), fmaxf(c[1], 0.f));
                    __half2 p1 = __floats2half2_rn(fmaxf(c[2], 0.f), fmaxf(c[3], 0.f));
                    u32 o0 = (u32)r0 * 512u + ((k8 ^ (u32)(r0 & 7)) << 4) + eb;
                    u32 o1 = (u32)r1 * 512u + ((k8 ^ (u32)(r1 & 7)) << 4) + eb;
                    *(u32*)(sm + SM_AH + o0) = *(u32*)&p0;
                    *(u32*)(sm + SM_AH + o1) = *(u32*)&p1;
                }
            }
        }

#pragma unroll
        for (int t = 0; t < 2; ++t)
#pragma unroll
            for (int j = 0; j < 8; ++j)
#pragma unroll
                for (int c = 0; c < 4; ++c) acc[t][j][c] = 0.f;

        // ---- GEMM2 ----
        gemm_stage<4>(smb, smb + SM_AH, (const uint4*)g_B2, acc, tid, lane, wm, wn);

        // ---- epilogue 2: relu -> gmem (registers only; no smem access) ----
        {
            int mbase = tile * 64;
#pragma unroll
            for (int t = 0; t < 2; ++t) {
                int r0 = mbase + wm + 16 * t + (lane >> 2);
                int r1 = r0 + 8;
#pragma unroll
                for (int j = 0; j < 8; ++j) {
                    float* c = acc[t][j];
                    int col = wn + 8 * j + 2 * (lane & 3);
                    if (r0 < N) {
                        float2 v = make_float2(fmaxf(c[0], 0.f), fmaxf(c[1], 0.f));
                        *(float2*)(out + (size_t)r0 * 256 + col) = v;
                    }
                    if (r1 < N) {
                        float2 v = make_float2(fmaxf(c[2], 0.f), fmaxf(c[3], 0.f));
                        *(float2*)(out + (size_t)r1 * 256 + col) = v;
                    }
                }
            }
        }
        __syncthreads();   // GEMM2 A/B reads done before next tile's smem writes
    }
}

// ---------------- host launcher ---------------------------------------------------
extern "C" void kernel_launch(void* const* d_in, const int* in_sizes, int n_in,
                              void* d_out, int out_size)
{
    int iL = -1, iImg = -1, iB = -1, iY = -1, iX = -1;
    int iWl1 = -1, iWl2 = -1, iWc1 = -1, iWc2 = -1, iWf1 = -1, iWf2 = -1;
    for (int i = 0; i < n_in; ++i) {
        int s = in_sizes[i];
        if      (s == BB * C_C * SPATIAL)      iImg = i;
        else if (s == CH_ALL * CH_HID)         { if (iWl1 < 0) iWl1 = i; else iWc1 = i; }
        else if (s == CH_HID * C_L)            { if (iWl2 < 0) iWl2 = i; else iWc2 = i; }
        else if (s == C_OUT * C_OUT)           { if (iWf1 < 0) iWf1 = i; else iWf2 = i; }
        else if (s % C_L == 0 && s >= 1000000) iL = i;
        else                                   { if (iB < 0) iB = i; else if (iY < 0) iY = i; else iX = i; }
    }
    const float* lidar = (const float*)d_in[iL];
    const float* img   = (const float*)d_in[iImg];
    const int*   bidx  = (const int*)d_in[iB];
    const int*   yidx  = (const int*)d_in[iY];
    const int*   xidx  = (const int*)d_in[iX];
    const float* Wl1   = (const float*)d_in[iWl1];
    const float* Wl2   = (const float*)d_in[iWl2];
    const float* Wc1   = (const float*)d_in[iWc1];
    const float* Wc2   = (const float*)d_in[iWc2];
    const float* Wf1   = (const float*)d_in[iWf1];
    const float* Wf2   = (const float*)d_in[iWf2];
    float* out = (float*)d_out;
    const int N = in_sizes[iL] / C_L;
    const int nchunks = (N + MM_CHUNK - 1) / MM_CHUNK;
    const int ntiles  = (N + 63) / 64;
    int gridf = ntiles < GRID_F ? ntiles : GRID_F;

    cudaFuncSetAttribute(fused_mma_kernel, cudaFuncAttributeMaxDynamicSharedMemorySize, SMEM_TOTAL);

    prep_kernel<<<TP_BLKS + 512 + 8, 256>>>(img, Wf1, Wf2);
    minmax_kernel<<<nchunks + 1, 256>>>(lidar, bidx, yidx, xidx, N, nchunks);
    mlp1_kernel<<<CH_HID, 256>>>(Wl1, Wc1);
    mlp2_kernel<<<128, 256>>>(Wl2, Wc2);
    hc_kernel<<<128, 256>>>(Wf1);
    fused_mma_kernel<<<gridf, 256, SMEM_TOTAL>>>(lidar, bidx, yidx, xidx, out, N, ntiles);
    (void)out_size;
}

// round 17
// speedup vs baseline: 1.3008x; 1.1007x over previous
#include <cuda_runtime.h>
#include <cuda_fp16.h>
#include <math.h>

// Problem constants (fixed-shape problem)
#define BB 4
#define HH_ 180
#define WW 180
#define SPATIAL (HH_ * WW)       // 32400
#define C_L 128
#define C_C 128
#define CH_ALL 512
#define CH_HID 170
#define C_OUT 256

typedef unsigned int u32;
typedef unsigned long long u64;

// ---- fused kernel smem map (bytes) ----
// A/h: [64m][256k] fp16 swizzled  : 0     .. 32767
// B buf0/buf1                      : 32768 .. 98303
// sbv[64] + stile[4] (+pad)        : 98304 .. 98575
#define SM_AH 0
#define SM_B  32768
#define SM_SB 98304
#define SMEM_TOTAL 98576

#define GRID_F 304    // 2 CTAs x 152 SMs (GB300)
#define MM_CHUNK 64

// ---------------- device scratch ----------------------------------------------
__device__ __align__(16) float g_imgT[SPATIAL * C_C];     // img batch0 [pixel][chan]
__device__ unsigned g_keys[BB * CH_ALL];                  // encoded min/max keys
__device__ __align__(16) float g_hid[2][BB][CH_HID];
__device__ __align__(16) float g_att_l[BB * C_L];
__device__ __align__(16) float g_att_c[BB * C_C];
__device__ __align__(16) float g_hc[BB * C_OUT];          // per-batch GEMM1 cam bias
__device__ __align__(16) __half g_B1[65536];              // pre-swizzled fp16 weights
__device__ __align__(16) __half g_B2[65536];
__device__ int g_tile_ctr;                                // dynamic tile ticket

// ---------------- helpers -------------------------------------------------------
__device__ __forceinline__ u32 smem_u32(const void* p) {
    u32 r;
    asm("{ .reg .u64 t; cvta.to.shared.u64 t, %1; cvt.u32.u64 %0, t; }" : "=r"(r) : "l"(p));
    return r;
}
__device__ __forceinline__ void cp16(u32 dst, const void* src) {
    asm volatile("cp.async.cg.shared.global [%0], [%1], 16;" :: "r"(dst), "l"(src) : "memory");
}
__device__ __forceinline__ void cp_commit() { asm volatile("cp.async.commit_group;" ::: "memory"); }
__device__ __forceinline__ void cp_wait0()  { asm volatile("cp.async.wait_group 0;" ::: "memory"); }

__device__ __forceinline__ void ldsm4(u32 a, u32 &r0, u32 &r1, u32 &r2, u32 &r3) {
    asm volatile("ldmatrix.sync.aligned.m8n8.x4.shared.b16 {%0,%1,%2,%3}, [%4];"
                 : "=r"(r0), "=r"(r1), "=r"(r2), "=r"(r3) : "r"(a));
}
__device__ __forceinline__ void mma16816(float* c, const u32* a, u32 b0, u32 b1) {
    asm volatile("mma.sync.aligned.m16n8k16.row.col.f32.f16.f16.f32 "
                 "{%0,%1,%2,%3}, {%4,%5,%6,%7}, {%8,%9}, {%0,%1,%2,%3};"
                 : "+f"(c[0]), "+f"(c[1]), "+f"(c[2]), "+f"(c[3])
                 : "r"(a[0]), "r"(a[1]), "r"(a[2]), "r"(a[3]), "r"(b0), "r"(b1));
}

// Order-preserving float <-> uint encoding for atomic min/max
__device__ __forceinline__ unsigned enc_f(float x) {
    unsigned u = __float_as_uint(x);
    return (u & 0x80000000u) ? ~u : (u | 0x80000000u);
}
__device__ __forceinline__ float dec_f(unsigned k) {
    unsigned u = (k & 0x80000000u) ? (k ^ 0x80000000u) : ~k;
    return __uint_as_float(u);
}
__device__ __forceinline__ void min4(float4 &d, float4 v) {
    d.x = fminf(d.x, v.x); d.y = fminf(d.y, v.y);
    d.z = fminf(d.z, v.z); d.w = fminf(d.w, v.w);
}
__device__ __forceinline__ void max4(float4 &d, float4 v) {
    d.x = fmaxf(d.x, v.x); d.y = fmaxf(d.y, v.y);
    d.z = fmaxf(d.z, v.z); d.w = fmaxf(d.w, v.w);
}

// ---------------- kernel A: prep = transpose + weight_prep + init_keys ----------
#define TP_BLKS (((SPATIAL + 31) / 32) * 4)    // 1013 * 4 = 4052
__global__ void __launch_bounds__(256) prep_kernel(
    const float* __restrict__ img,
    const float* __restrict__ Wf1, const float* __restrict__ Wf2)
{
    int blk = blockIdx.x;
    int tid = threadIdx.x;
    if (blk == 0 && tid == 0) g_tile_ctr = 0;   // reset dynamic scheduler each call
    if (blk < TP_BLKS) {
        __shared__ float tile[32][33];
        int bx = blk % 1013, by = blk / 1013;
        int p0 = bx * 32, c0 = by * 32;
        int tx = tid & 31, ty = tid >> 5;
#pragma unroll
        for (int j = 0; j < 4; ++j) {
            int c = c0 + ty + j * 8;
            int p = p0 + tx;
            if (p < SPATIAL) tile[ty + j * 8][tx] = img[c * SPATIAL + p];
        }
        __syncthreads();
#pragma unroll
        for (int j = 0; j < 4; ++j) {
            int p = p0 + ty + j * 8;
            int c = c0 + tx;
            if (p < SPATIAL) g_imgT[p * C_C + c] = tile[tx][ty + j * 8];
        }
    } else if (blk < TP_BLKS + 512) {
        int idx = (blk - TP_BLKS) * 256 + tid;   // 2 * 65536
        int mat = idx >> 16;
        int rem = idx & 65535;
        int k = rem >> 8;
        int n = rem & 255;
        const float* W = mat ? Wf2 : Wf1;
        __half hv = __float2half_rn(W[k * 256 + n]);
        int p = k >> 6, k8l = (k >> 3) & 7, e = k & 7;
        u32 off = (u32)p * 32768u + (u32)n * 128u + ((u32)(k8l ^ (n & 7)) << 4) + (u32)e * 2u;
        __half* wim = mat ? g_B2 : g_B1;
        *(unsigned short*)((char*)wim + off) = *(unsigned short*)&hv;
    } else {
        int i = (blk - TP_BLKS - 512) * 256 + tid;
        if (i < BB * CH_ALL) {
            int slot = i & (CH_ALL - 1);
            bool is_min = (slot < 128) || (slot >= 256 && slot < 384);
            g_keys[i] = is_min ? 0xFFFFFFFFu : 0x00000000u;
        }
    }
}

// ---------------- kernel B: minmax (+const_cam in the extra block) --------------
__device__ __forceinline__ void flush_mm(int b, int c, float mn, float mx) {
    int msl, xsl;
    if (c < 128) { msl = c;             xsl = 128 + c; }
    else         { msl = 256 + c - 128; xsl = 384 + c - 128; }
    atomicMin(&g_keys[b * CH_ALL + msl], enc_f(mn));
    atomicMax(&g_keys[b * CH_ALL + xsl], enc_f(mx));
}
__global__ void __launch_bounds__(256) minmax_kernel(
    const float* __restrict__ lidar, const int* __restrict__ batch_idx,
    const int* __restrict__ y_idx, const int* __restrict__ x_idx,
    int N, int nchunks)
{
    int tid = threadIdx.x;
    if ((int)blockIdx.x == nchunks) {    // const_cam block (b>=1 gathers pixel 32398)
        for (int i = tid; i < 384; i += 256) {
            int b = 1 + (i >> 7);
            int c = i & 127;
            unsigned e = enc_f(g_imgT[(size_t)(SPATIAL - 2) * C_C + c]);
            atomicMin(&g_keys[b * CH_ALL + 256 + c], e);
            atomicMax(&g_keys[b * CH_ALL + 384 + c], e);
        }
        return;
    }
    __shared__ int sb[MM_CHUNK];
    __shared__ int sr[MM_CHUNK];
    __shared__ float red[4][8][128];
    int n0 = blockIdx.x * MM_CHUNK;
    int cnt = N - n0; if (cnt > MM_CHUNK) cnt = MM_CHUNK;
    if (cnt <= 0) return;
    if (tid < cnt) {
        int n = n0 + tid;
        int b = batch_idx[n];
        int r = b * SPATIAL + y_idx[n] * WW + x_idx[n];
        if (r > SPATIAL - 2) r = SPATIAL - 2;
        sb[tid] = b; sr[tid] = r;
    }
    __syncthreads();

    if (cnt == MM_CHUNK && sb[0] == sb[MM_CHUNK - 1]) {
        // uniform chunk: 256 threads = 8 row-groups x 32 channel-quads
        const int rg = tid >> 5;
        const int c4 = tid & 31;
        const float4* lid4 = (const float4*)lidar;
        const bool do_cam = (sb[0] == 0);   // cam is constant for b>=1
        float4 mnl = make_float4( INFINITY,  INFINITY,  INFINITY,  INFINITY);
        float4 mxl = make_float4(-INFINITY, -INFINITY, -INFINITY, -INFINITY);
        float4 mnc = mnl, mxc = mxl;
        if (do_cam) {
            const float4* img4 = (const float4*)g_imgT;
#pragma unroll
            for (int i = 0; i < MM_CHUNK / 8; ++i) {
                int row = i * 8 + rg;
                float4 lv = lid4[(size_t)(n0 + row) * 32 + c4];
                float4 cv = img4[(size_t)sr[row] * 32 + c4];
                min4(mnl, lv); max4(mxl, lv);
                min4(mnc, cv); max4(mxc, cv);
            }
        } else {
#pragma unroll
            for (int i = 0; i < MM_CHUNK / 8; ++i) {
                int row = i * 8 + rg;
                float4 lv = lid4[(size_t)(n0 + row) * 32 + c4];
                min4(mnl, lv); max4(mxl, lv);
            }
        }
        int ch = c4 * 4;
        *(float4*)&red[0][rg][ch] = mnl;
        *(float4*)&red[1][rg][ch] = mxl;
        if (do_cam) {
            *(float4*)&red[2][rg][ch] = mnc;
            *(float4*)&red[3][rg][ch] = mxc;
        }
        __syncthreads();
        int c = tid;
        if (c < 128 || do_cam) {
            int qm = (c < 128) ? 0 : 2;
            int cc = c & 127;
            float mn = red[qm][0][cc], mx = red[qm + 1][0][cc];
#pragma unroll
            for (int g = 1; g < 8; ++g) {
                mn = fminf(mn, red[qm][g][cc]);
                mx = fmaxf(mx, red[qm + 1][g][cc]);
            }
            flush_mm(sb[0], c, mn, mx);
        }
    } else {
        const int c = tid & 255;
        if (tid < 256) {
            const bool cam = (c >= 128);
            const float* base = cam ? (g_imgT + (c - 128)) : (lidar + c);
            float mn = INFINITY, mx = -INFINITY;
            int cur = sb[0];
            for (int i = 0; i < cnt; ++i) {
                int b = sb[i];
                if (b != cur) { flush_mm(cur, c, mn, mx); cur = b; mn = INFINITY; mx = -INFINITY; }
                float v = cam ? base[(size_t)sr[i] * C_C] : base[(size_t)(n0 + i) * C_L];
                mn = fminf(mn, v); mx = fmaxf(mx, v);
            }
            flush_mm(cur, c, mn, mx);
        }
    }
}

// ---------------- kernel C: gating MLP layer 1 (warp per output) ----------------
__global__ void __launch_bounds__(256) mlp1_kernel(
    const float* __restrict__ Wl1, const float* __restrict__ Wc1)
{
    int gw   = blockIdx.x * 8 + (threadIdx.x >> 5);
    int lane = threadIdx.x & 31;
    int net  = gw / (BB * CH_HID);
    int rem  = gw % (BB * CH_HID);
    int b    = rem / CH_HID;
    int j    = rem % CH_HID;
    const float* W = net ? Wc1 : Wl1;
    float s = 0.f;
#pragma unroll
    for (int t = 0; t < 16; ++t) {
        int k = lane + 32 * t;
        s = fmaf(dec_f(g_keys[b * CH_ALL + k]), W[k * CH_HID + j], s);
    }
#pragma unroll
    for (int o = 16; o; o >>= 1) s += __shfl_xor_sync(0xffffffffu, s, o);
    if (lane == 0) g_hid[net][b][j] = fmaxf(s, 0.f);
}

// ---------------- kernel D: gating MLP layer 2 + sigmoid (warp per output) ------
__global__ void __launch_bounds__(256) mlp2_kernel(
    const float* __restrict__ Wl2, const float* __restrict__ Wc2)
{
    int gw   = blockIdx.x * 8 + (threadIdx.x >> 5);   // 0..1023
    int lane = threadIdx.x & 31;
    int net  = gw >> 9, rem = gw & 511;
    int b    = rem >> 7, cc = rem & 127;
    const float* W2 = net ? Wc2 : Wl2;
    const float* h  = g_hid[net][b];
    float s = 0.f;
#pragma unroll
    for (int t = 0; t < 6; ++t) {
        int k = lane + 32 * t;
        if (k < CH_HID) s = fmaf(h[k], W2[k * 128 + cc], s);
    }
#pragma unroll
    for (int o = 16; o; o >>= 1) s += __shfl_xor_sync(0xffffffffu, s, o);
    if (lane == 0) {
        float v = fmaxf(s, 0.f);
        (net ? g_att_c : g_att_l)[b * 128 + cc] = 1.f / (1.f + expf(-v));
    }
}

// ---------------- kernel E: per-batch GEMM1 cam bias (warp per output) ----------
__global__ void __launch_bounds__(256) hc_kernel(const float* __restrict__ Wf1) {
    int gw   = blockIdx.x * 8 + (threadIdx.x >> 5);   // 0..1023
    int lane = threadIdx.x & 31;
    int b    = gw >> 8, n = gw & 255;
    float s = 0.f;
#pragma unroll
    for (int t = 0; t < 4; ++t) {
        int k = lane + 32 * t;
        float gc = g_att_c[b * 128 + k] * g_imgT[(size_t)(SPATIAL - 2) * C_C + k];
        s = fmaf(gc, Wf1[(128 + k) * 256 + n], s);
    }
#pragma unroll
    for (int o = 16; o; o >>= 1) s += __shfl_xor_sync(0xffffffffu, s, o);
    if (lane == 0) g_hc[b * 256 + n] = s;
}

// ---------------- B panel-0 prefetch (buf0) ---------------------------------------
__device__ __forceinline__ void preload_B0(u32 smb, const uint4* __restrict__ Bimg, int tid) {
    u32 dst = smb + SM_B + (u32)tid * 16u;
    const uint4* s = Bimg + tid;
#pragma unroll
    for (int i = 0; i < 8; ++i) cp16(dst + i * 4096u, s + i * 256);
    cp_commit();
}

// ---------------- fused GEMM stage (M=64, fp16 single-term, NP panels) -----------
// Panel 0 must already be prefetched into buf0 (one pending commit group).
// One __syncthreads per panel: [wait; sync; issue-next; compute].  NO trailing
// sync — caller must __syncthreads() before reusing A or B smem.
template<int NP>
__device__ __forceinline__ void gemm_stage(
    u32 smb, u32 Abase, const uint4* __restrict__ Bimg,
    float acc[2][8][4], int tid, int lane, int wm, int wn)
{
    const u32 Bb = smb + SM_B;
#pragma unroll 1
    for (int p = 0; p < NP; ++p) {
        cp_wait0();
        __syncthreads();
        if (p < NP - 1) {
            u32 dst = Bb + (u32)((p + 1) & 1) * 32768u + (u32)tid * 16u;
            const uint4* s = Bimg + (p + 1) * 2048 + tid;
#pragma unroll
            for (int i = 0; i < 8; ++i) cp16(dst + i * 4096u, s + i * 256);
            cp_commit();
        }
        u32 B = Bb + (u32)(p & 1) * 32768u;
#pragma unroll
        for (int s = 0; s < 4; ++s) {
            int k8 = p * 8 + s * 2 + (lane >> 4);
            int arow = wm + (lane & 15);
            u32 aoff = (u32)arow * 512u + ((u32)(k8 ^ (arow & 7)) << 4);
            u32 ah[2][4];
            ldsm4(Abase + aoff,          ah[0][0], ah[0][1], ah[0][2], ah[0][3]);
            ldsm4(Abase + aoff + 8192u,  ah[1][0], ah[1][1], ah[1][2], ah[1][3]);
            int k8h = s * 2 + (lane >> 4);
            u32 bh[8][2];
#pragma unroll
            for (int j16 = 0; j16 < 4; ++j16) {
                int brow = wn + j16 * 16 + (lane & 15);
                u32 rb = B + (u32)brow * 128u;
                u32 r0, r1, r2, r3;
                ldsm4(rb + ((u32)(k8h ^ (brow & 7)) << 4), r0, r1, r2, r3);
                bh[2*j16][0] = r0;   bh[2*j16][1] = r2;
                bh[2*j16+1][0] = r1; bh[2*j16+1][1] = r3;
            }
#pragma unroll
            for (int t = 0; t < 2; ++t)
#pragma unroll
                for (int j = 0; j < 8; ++j)
                    mma16816(acc[t][j], ah[t], bh[j][0], bh[j][1]);
        }
    }
}

// ---------------- kernel F: persistent fused gate+GEMM1+ReLU+GEMM2+ReLU ----------
__global__ void __launch_bounds__(256, 2) fused_mma_kernel(
    const float* __restrict__ lidar,
    const int* __restrict__ batch_idx,
    const int* __restrict__ y_idx,
    const int* __restrict__ x_idx,
    float* __restrict__ out, int N, int ntiles)
{
    extern __shared__ char sm[];
    const u32 smb = smem_u32(sm);
    int* sbv = (int*)(sm + SM_SB);       // [64] batch ids
    int* stile = sbv + 64;               // [1] tile ticket (within SMEM_TOTAL)
    const int tid  = threadIdx.x;
    const int lane = tid & 31;
    const int wid  = tid >> 5;
    const int wm   = (wid & 1) * 32;
    const int wn   = (wid >> 1) * 64;

    for (;;) {
        // ---- dynamic tile ticket (evens out short/full duration mix) ----
        if (tid == 0) *stile = atomicAdd(&g_tile_ctr, 1);
        __syncthreads();
        int tile = *stile;
        if (tile >= ntiles) break;

        int first_n = tile * 64;
        if (first_n >= N) first_n = N - 1;
        const bool short_tile = (batch_idx[first_n] >= 1);

        // prefetch GEMM1 B panel 0 — overlaps the phase-1 gather below.
        preload_B0(smb, (const uint4*)g_B1, tid);

        // ---- phase 1: gather + gate + fp16 cvt into A smem (swizzled) ----
        {
            int m = tid >> 2, q = tid & 3;
            int n = tile * 64 + m;
            int nn = n < N ? n : N - 1;
            int b = batch_idx[nn];
            if (q == 0) sbv[m] = b;
            if (!(short_tile && q >= 2)) {
                const float* src;
                const float* att;
                if (q < 2) { src = lidar + (size_t)nn * C_L; att = g_att_l + b * 128; }
                else {
                    int r = b * SPATIAL + y_idx[nn] * WW + x_idx[nn];
                    if (r > SPATIAL - 2) r = SPATIAL - 2;
                    src = g_imgT + (size_t)r * C_C; att = g_att_c + b * 128;
                }
                const float4* s4 = (const float4*)src;
                const float4* g4 = (const float4*)att;
                int ho = (q & 1) * 16;
                u32 rowb = (u32)m * 512u;
                u32 xm = (u32)(m & 7);
#pragma unroll
                for (int i = 0; i < 8; ++i) {
                    float4 a0 = s4[ho + 2*i], a1 = s4[ho + 2*i + 1];
                    float4 q0 = g4[ho + 2*i], q1 = g4[ho + 2*i + 1];
                    __half2 h0 = __floats2half2_rn(a0.x*q0.x, a0.y*q0.y);
                    __half2 h1 = __floats2half2_rn(a0.z*q0.z, a0.w*q0.w);
                    __half2 h2 = __floats2half2_rn(a1.x*q1.x, a1.y*q1.y);
                    __half2 h3 = __floats2half2_rn(a1.z*q1.z, a1.w*q1.w);
                    uint4 H = make_uint4(*(u32*)&h0, *(u32*)&h1, *(u32*)&h2, *(u32*)&h3);
                    u32 k8 = (u32)(q * 8 + i);
                    u32 off = rowb + ((k8 ^ xm) << 4);
                    *(uint4*)(sm + SM_AH + off) = H;
                }
            }
        }
        __syncthreads();   // sbv + A visible (acc init below reads sbv)

        // ---- acc init: zero (full) or per-row cam bias hc[b] (short) ----
        float acc[2][8][4];
        if (short_tile) {
#pragma unroll
            for (int t = 0; t < 2; ++t) {
                int r0 = wm + 16 * t + (lane >> 2);
                int r1 = r0 + 8;
                const float* h0 = g_hc + sbv[r0] * 256;
                const float* h1 = g_hc + sbv[r1] * 256;
#pragma unroll
                for (int j = 0; j < 8; ++j) {
                    int col = wn + 8 * j + 2 * (lane & 3);
                    acc[t][j][0] = h0[col];   acc[t][j][1] = h0[col + 1];
                    acc[t][j][2] = h1[col];   acc[t][j][3] = h1[col + 1];
                }
            }
        } else {
#pragma unroll
            for (int t = 0; t < 2; ++t)
#pragma unroll
                for (int j = 0; j < 8; ++j)
#pragma unroll
                    for (int c = 0; c < 4; ++c) acc[t][j][c] = 0.f;
        }

        // ---- GEMM1: K=128 (short) or K=256 (full) ----
        if (short_tile)
            gemm_stage<2>(smb, smb + SM_AH, (const uint4*)g_B1, acc, tid, lane, wm, wn);
        else
            gemm_stage<4>(smb, smb + SM_AH, (const uint4*)g_B1, acc, tid, lane, wm, wn);
        __syncthreads();   // all GEMM1 A/B reads complete

        // prefetch GEMM2 B panel 0 — overlaps epilogue 1
        preload_B0(smb, (const uint4*)g_B2, tid);

        // ---- epilogue 1: relu + fp16 cvt -> h (overwrites A smem; safe after sync;
        //      GEMM2's first in-loop sync publishes these writes before ldsm) ----
        {
#pragma unroll
            for (int t = 0; t < 2; ++t) {
                int r0 = wm + 16 * t + (lane >> 2);
                int r1 = r0 + 8;
#pragma unroll
                for (int j = 0; j < 8; ++j) {
                    float* c = acc[t][j];
                    u32 k8 = (u32)((wn >> 3) + j);
                    u32 eb = (u32)(lane & 3) * 4u;
                    __half2 p0 = __floats2half2_rn(fmaxf(c[0], 0.f), fmaxf(c[1], 0.f));
                    __half2 p1 = __floats2half2_rn(fmaxf(c[2], 0.f), fmaxf(c[3], 0.f));
                    u32 o0 = (u32)r0 * 512u + ((k8 ^ (u32)(r0 & 7)) << 4) + eb;
                    u32 o1 = (u32)r1 * 512u + ((k8 ^ (u32)(r1 & 7)) << 4) + eb;
                    *(u32*)(sm + SM_AH + o0) = *(u32*)&p0;
                    *(u32*)(sm + SM_AH + o1) = *(u32*)&p1;
                }
            }
        }

#pragma unroll
        for (int t = 0; t < 2; ++t)
#pragma unroll
            for (int j = 0; j < 8; ++j)
#pragma unroll
                for (int c = 0; c < 4; ++c) acc[t][j][c] = 0.f;

        // ---- GEMM2 ----
        gemm_stage<4>(smb, smb + SM_AH, (const uint4*)g_B2, acc, tid, lane, wm, wn);

        // ---- epilogue 2: relu -> gmem (registers only; no smem access) ----
        {
            int mbase = tile * 64;
#pragma unroll
            for (int t = 0; t < 2; ++t) {
                int r0 = mbase + wm + 16 * t + (lane >> 2);
                int r1 = r0 + 8;
#pragma unroll
                for (int j = 0; j < 8; ++j) {
                    float* c = acc[t][j];
                    int col = wn + 8 * j + 2 * (lane & 3);
                    if (r0 < N) {
                        float2 v = make_float2(fmaxf(c[0], 0.f), fmaxf(c[1], 0.f));
                        *(float2*)(out + (size_t)r0 * 256 + col) = v;
                    }
                    if (r1 < N) {
                        float2 v = make_float2(fmaxf(c[2], 0.f), fmaxf(c[3], 0.f));
                        *(float2*)(out + (size_t)r1 * 256 + col) = v;
                    }
                }
            }
        }
        __syncthreads();   // GEMM2 A/B reads + stile read done before next tile
    }
}

// ---------------- host launcher ---------------------------------------------------
extern "C" void kernel_launch(void* const* d_in, const int* in_sizes, int n_in,
                              void* d_out, int out_size)
{
    int iL = -1, iImg = -1, iB = -1, iY = -1, iX = -1;
    int iWl1 = -1, iWl2 = -1, iWc1 = -1, iWc2 = -1, iWf1 = -1, iWf2 = -1;
    for (int i = 0; i < n_in; ++i) {
        int s = in_sizes[i];
        if      (s == BB * C_C * SPATIAL)      iImg = i;
        else if (s == CH_ALL * CH_HID)         { if (iWl1 < 0) iWl1 = i; else iWc1 = i; }
        else if (s == CH_HID * C_L)            { if (iWl2 < 0) iWl2 = i; else iWc2 = i; }
        else if (s == C_OUT * C_OUT)           { if (iWf1 < 0) iWf1 = i; else iWf2 = i; }
        else if (s % C_L == 0 && s >= 1000000) iL = i;
        else                                   { if (iB < 0) iB = i; else if (iY < 0) iY = i; else iX = i; }
    }
    const float* lidar = (const float*)d_in[iL];
    const float* img   = (const float*)d_in[iImg];
    const int*   bidx  = (const int*)d_in[iB];
    const int*   yidx  = (const int*)d_in[iY];
    const int*   xidx  = (const int*)d_in[iX];
    const float* Wl1   = (const float*)d_in[iWl1];
    const float* Wl2   = (const float*)d_in[iWl2];
    const float* Wc1   = (const float*)d_in[iWc1];
    const float* Wc2   = (const float*)d_in[iWc2];
    const float* Wf1   = (const float*)d_in[iWf1];
    const float* Wf2   = (const float*)d_in[iWf2];
    float* out = (float*)d_out;
    const int N = in_sizes[iL] / C_L;
    const int nchunks = (N + MM_CHUNK - 1) / MM_CHUNK;
    const int ntiles  = (N + 63) / 64;
    int gridf = ntiles < GRID_F ? ntiles : GRID_F;

    cudaFuncSetAttribute(fused_mma_kernel, cudaFuncAttributeMaxDynamicSharedMemorySize, SMEM_TOTAL);

    prep_kernel<<<TP_BLKS + 512 + 8, 256>>>(img, Wf1, Wf2);
    minmax_kernel<<<nchunks + 1, 256>>>(lidar, bidx, yidx, xidx, N, nchunks);
    mlp1_kernel<<<CH_HID, 256>>>(Wl1, Wc1);
    mlp2_kernel<<<128, 256>>>(Wl2, Wc2);
    hc_kernel<<<128, 256>>>(Wf1);
    fused_mma_kernel<<<gridf, 256, SMEM_TOTAL>>>(lidar, bidx, yidx, xidx, out, N, ntiles);
    (void)out_size;
}